// round 4
// baseline (speedup 1.0000x reference)
#include <cuda_runtime.h>
#include <math.h>

// Problem dims
#define TSTEPS 63
#define BATCH  32
#define SEQ    64
#define HID    1024
#define EMB    512
#define VOC    32000
#define GATES  4096
#define HC     2048
#define MROWS  (TSTEPS*BATCH)   // 2016
#define NCTA   148

// ---------------- scratch (static device globals; no runtime alloc) -------------
__device__ float g_Emb [MROWS*EMB];          //  4 MB  gathered embeddings, row r = t*32+b
__device__ float g_XP  [MROWS*GATES];        // 33 MB  x@W_ih^T + (b_ih+b_hh)
__device__ float g_h   [BATCH*HID];
__device__ float g_c   [BATCH*HID];
__device__ float g_hcat[BATCH*HC];           // [h | context]
__device__ float g_gpart[4][BATCH*GATES];    //  2 MB  split-K partials of h@W_hh^T
__device__ float g_dpart[16][MROWS*HID];     // 132 MB split-K partials of hcat@W_w^T (per t)
__device__ float g_Dec [MROWS*HID];          //  8 MB  tanh(dec_raw + b_w)
__device__ unsigned g_barcnt = 0;
__device__ unsigned g_bargen = 0;

// ---------------- software grid barrier (all 148 CTAs resident) ----------------
__device__ __forceinline__ void gridbar(){
    __syncthreads();
    if (threadIdx.x == 0){
        __threadfence();
        unsigned gen = *((volatile unsigned*)&g_bargen);
        if (atomicAdd(&g_barcnt, 1u) == gridDim.x - 1u){
            g_barcnt = 0u;
            __threadfence();
            atomicExch(&g_bargen, gen + 1u);
        } else {
            while (*((volatile unsigned*)&g_bargen) == gen) __nanosleep(64);
        }
    }
    __syncthreads();
}

// half-CTA named barrier (128 threads, warp-aligned halves)
__device__ __forceinline__ void hbar(int half){
    asm volatile("bar.sync %0, 128;" :: "r"(half + 1));
}

// ---------------- init: copy h0/c0 -------------------------------------------
__global__ void k_init(const float* __restrict__ h0, const float* __restrict__ c0){
    int i = blockIdx.x*blockDim.x + threadIdx.x;
    if (i < BATCH*HID){ g_h[i] = h0[i]; g_c[i] = c0[i]; }
}

// ---------------- embedding gather -------------------------------------------
__global__ void k_embed(const int* __restrict__ tgt, const float* __restrict__ emb){
    int r = blockIdx.x;              // 0..2015
    int t = r >> 5, b = r & 31;
    int tok = tgt[b*64 + t];         // tgt is (B=32, T=64) row-major; cols [0, T-1)
    const float4* src = (const float4*)(emb + (size_t)tok*EMB);
    float4*       dst = (float4*)(g_Emb + (size_t)r*EMB);
    dst[threadIdx.x] = src[threadIdx.x];
}

// ---------------- XP = Emb @ W_ih^T + b_ih + b_hh  (2016 x 4096, K=512) ------
__global__ void k_xp(const float* __restrict__ B,
                     const float* __restrict__ bih, const float* __restrict__ bhh){
    const int M = MROWS, N = GATES, K = EMB;
    __shared__ float sA[16][68];
    __shared__ float sB[16][68];
    int bm = blockIdx.y*64, bn = blockIdx.x*64;
    int tid = threadIdx.x;
    int tm = (tid>>4)<<2, tn = (tid&15)<<2;
    int lm = tid>>2, lk = (tid&3)<<2;
    float acc[4][4];
    #pragma unroll
    for(int i=0;i<4;i++){ acc[i][0]=0.f; acc[i][1]=0.f; acc[i][2]=0.f; acc[i][3]=0.f; }
    for (int k0=0;k0<K;k0+=16){
        int gm = bm+lm;
        float4 av = (gm < M) ? *(const float4*)(g_Emb + (size_t)gm*K + k0 + lk)
                             : make_float4(0.f,0.f,0.f,0.f);
        sA[lk+0][lm]=av.x; sA[lk+1][lm]=av.y; sA[lk+2][lm]=av.z; sA[lk+3][lm]=av.w;
        float4 bv = *(const float4*)(B + (size_t)(bn+lm)*K + k0 + lk);
        sB[lk+0][lm]=bv.x; sB[lk+1][lm]=bv.y; sB[lk+2][lm]=bv.z; sB[lk+3][lm]=bv.w;
        __syncthreads();
        #pragma unroll
        for(int kk=0;kk<16;kk++){
            float4 a = *(const float4*)&sA[kk][tm];
            float4 b = *(const float4*)&sB[kk][tn];
            float aa[4]={a.x,a.y,a.z,a.w}, bb[4]={b.x,b.y,b.z,b.w};
            #pragma unroll
            for(int i=0;i<4;i++)
                #pragma unroll
                for(int j=0;j<4;j++) acc[i][j] += aa[i]*bb[j];
        }
        __syncthreads();
    }
    #pragma unroll
    for(int i=0;i<4;i++){
        int m = bm+tm+i;
        if (m < M){
            #pragma unroll
            for(int j=0;j<4;j++){
                int n = bn+tn+j;
                g_XP[(size_t)m*N + n] = acc[i][j] + bih[n] + bhh[n];
            }
        }
    }
}

// ---------------- gates task: g_gpart[Ks] = h @ W_hh^T (N-tile 64, K-slice 256)
__device__ __forceinline__ void gates_task(const float* __restrict__ B, int task, int lt,
                                           float (*sA)[36], float (*sB)[68], int half){
    const int N = GATES, K = HID;
    int bn   = (task & 63) * 64;
    int Koff = (task >> 6) * 256;
    int tm = (lt>>4)<<2, tn = (lt&15)<<2;
    int lm = lt>>2, lk = (lt&3)<<2;
    float acc[4][4];
    #pragma unroll
    for(int i=0;i<4;i++){ acc[i][0]=0.f; acc[i][1]=0.f; acc[i][2]=0.f; acc[i][3]=0.f; }
    for (int k0=0;k0<256;k0+=16){
        float4 av = __ldcs((const float4*)(g_h + (size_t)lm*K + Koff + k0 + lk));
        sA[lk+0][lm]=av.x; sA[lk+1][lm]=av.y; sA[lk+2][lm]=av.z; sA[lk+3][lm]=av.w;
        #pragma unroll
        for (int r=0;r<2;r++){
            int n = lm + 32*r;
            float4 bv = *(const float4*)(B + (size_t)(bn+n)*K + Koff + k0 + lk);
            sB[lk+0][n]=bv.x; sB[lk+1][n]=bv.y; sB[lk+2][n]=bv.z; sB[lk+3][n]=bv.w;
        }
        hbar(half);
        #pragma unroll
        for(int kk=0;kk<16;kk++){
            float4 a = *(const float4*)&sA[kk][tm];
            float4 b = *(const float4*)&sB[kk][tn];
            float aa[4]={a.x,a.y,a.z,a.w}, bb[4]={b.x,b.y,b.z,b.w};
            #pragma unroll
            for(int i=0;i<4;i++)
                #pragma unroll
                for(int j=0;j<4;j++) acc[i][j] += aa[i]*bb[j];
        }
        hbar(half);
    }
    float* dst = g_gpart[task >> 6];
    #pragma unroll
    for(int i=0;i<4;i++)
        #pragma unroll
        for(int j=0;j<4;j++)
            dst[(size_t)(tm+i)*N + bn+tn+j] = acc[i][j];
}

// ---------------- dec task: g_dpart[Ks][t] = hcat @ W_w^T (N-tile 64, K-slice 128)
__device__ __forceinline__ void dec_task(const float* __restrict__ B, int task, int lt,
                                         float (*sA)[36], float (*sB)[68], int half, int t){
    const int N = HID, K = HC;
    int bn   = (task & 15) * 64;
    int Koff = (task >> 4) * 128;
    int tm = (lt>>4)<<2, tn = (lt&15)<<2;
    int lm = lt>>2, lk = (lt&3)<<2;
    float acc[4][4];
    #pragma unroll
    for(int i=0;i<4;i++){ acc[i][0]=0.f; acc[i][1]=0.f; acc[i][2]=0.f; acc[i][3]=0.f; }
    for (int k0=0;k0<128;k0+=16){
        float4 av = __ldcs((const float4*)(g_hcat + (size_t)lm*K + Koff + k0 + lk));
        sA[lk+0][lm]=av.x; sA[lk+1][lm]=av.y; sA[lk+2][lm]=av.z; sA[lk+3][lm]=av.w;
        #pragma unroll
        for (int r=0;r<2;r++){
            int n = lm + 32*r;
            float4 bv = *(const float4*)(B + (size_t)(bn+n)*K + Koff + k0 + lk);
            sB[lk+0][n]=bv.x; sB[lk+1][n]=bv.y; sB[lk+2][n]=bv.z; sB[lk+3][n]=bv.w;
        }
        hbar(half);
        #pragma unroll
        for(int kk=0;kk<16;kk++){
            float4 a = *(const float4*)&sA[kk][tm];
            float4 b = *(const float4*)&sB[kk][tn];
            float aa[4]={a.x,a.y,a.z,a.w}, bb[4]={b.x,b.y,b.z,b.w};
            #pragma unroll
            for(int i=0;i<4;i++)
                #pragma unroll
                for(int j=0;j<4;j++) acc[i][j] += aa[i]*bb[j];
        }
        hbar(half);
    }
    float* dst = g_dpart[task >> 4] + (size_t)t*BATCH*HID;
    #pragma unroll
    for(int i=0;i<4;i++)
        #pragma unroll
        for(int j=0;j<4;j++)
            dst[(size_t)(tm+i)*N + bn+tn+j] = acc[i][j];
}

// ---------------- fused cell + attention for one batch (CTA b, 256 threads) --
__device__ void cell_attn(const float* __restrict__ enc, int b, int tid, int t,
                          float* sh, float* ss){
    const float* xp = g_XP + ((size_t)t*BATCH + b)*GATES;
    size_t gbase = (size_t)b*GATES;
    #pragma unroll
    for (int r=0;r<4;r++){
        int j = tid + 256*r;
        float gi = __ldcs(xp + j);
        float gf = __ldcs(xp + 1024 + j);
        float gg = __ldcs(xp + 2048 + j);
        float go = __ldcs(xp + 3072 + j);
        #pragma unroll
        for (int s=0;s<4;s++){
            const float* gp = g_gpart[s] + gbase;
            gi += gp[j]; gf += gp[1024+j]; gg += gp[2048+j]; go += gp[3072+j];
        }
        float i_ = 1.f/(1.f+expf(-gi));
        float f_ = 1.f/(1.f+expf(-gf));
        float g_ = tanhf(gg);
        float o_ = 1.f/(1.f+expf(-go));
        int idx  = b*HID + j;
        float c  = f_*g_c[idx] + i_*g_;
        g_c[idx] = c;
        float h  = o_*tanhf(c);
        g_h[idx] = h;
        g_hcat[(size_t)b*HC + j] = h;
        sh[j] = h;
    }
    __syncthreads();
    int warp = tid>>5, lane = tid&31;
    for (int s=warp; s<SEQ; s+=8){
        const float* e = enc + ((size_t)b*SEQ + s)*HID;
        float acc = 0.f;
        for (int k=lane;k<HID;k+=32) acc += sh[k]*__ldcs(e + k);
        #pragma unroll
        for(int o=16;o;o>>=1) acc += __shfl_xor_sync(0xffffffffu, acc, o);
        if (!lane) ss[s] = acc;
    }
    __syncthreads();
    if (tid == 0){
        float mx = -1e30f;
        for(int s=0;s<SEQ;s++) mx = fmaxf(mx, ss[s]);
        float sum = 0.f;
        for(int s=0;s<SEQ;s++){ float e = expf(ss[s]-mx); ss[s]=e; sum+=e; }
        float inv = 1.f/sum;
        for(int s=0;s<SEQ;s++) ss[s] *= inv;
    }
    __syncthreads();
    int j = tid<<2;
    float c0=0.f,c1=0.f,c2=0.f,c3=0.f;
    for(int s=0;s<SEQ;s++){
        float a = ss[s];
        float4 v = __ldcs((const float4*)(enc + ((size_t)b*SEQ+s)*HID + j));
        c0 += a*v.x; c1 += a*v.y; c2 += a*v.z; c3 += a*v.w;
    }
    *(float4*)(g_hcat + (size_t)b*HC + HID + j) = make_float4(c0,c1,c2,c3);
}

// ---------------- persistent recurrence kernel --------------------------------
__global__ void __launch_bounds__(256, 1)
k_loop(const float* __restrict__ enc, const float* __restrict__ Whh,
       const float* __restrict__ Ww){
    __shared__ float sA[2][16][36];
    __shared__ float sB[2][16][68];
    __shared__ float sh[HID];
    __shared__ float ss[SEQ];
    int cta = blockIdx.x, tid = threadIdx.x;
    int half = tid >> 7, lt = tid & 127;
    int task = cta + NCTA*half;          // 0..295; valid tasks are < 256
    for (int t = 0; t < TSTEPS; t++){
        if (task < 256) gates_task(Whh, task, lt, sA[half], sB[half], half);
        gridbar();
        if (cta < BATCH) cell_attn(enc, cta, tid, t, sh, ss);
        gridbar();
        if (task < 256) dec_task(Ww, task, lt, sA[half], sB[half], half, t);
        gridbar();
    }
}

// ---------------- tanh reduce over the 16 dec slices --------------------------
__global__ void k_tanh(const float* __restrict__ bw){
    int idx = blockIdx.x*blockDim.x + threadIdx.x;   // 2016*1024
    float s = bw[idx & 1023];
    #pragma unroll
    for(int p=0;p<16;p++) s += g_dpart[p][idx];
    g_Dec[idx] = tanhf(s);
}

// ---------------- output GEMM: Dec(2016x1024) @ W_out^T(1024x32000) ----------
__global__ void k_out(const float* __restrict__ B,
                      const float* __restrict__ bout, float* __restrict__ out){
    const int M = MROWS, N = VOC, K = HID;
    __shared__ float sA[16][132];
    __shared__ float sB[16][132];
    int bm = blockIdx.y*128, bn = blockIdx.x*128;
    int tid = threadIdx.x;                    // 256
    int tm = (tid>>4)<<3, tn = (tid&15)<<3;
    int lm = tid>>1, lk = (tid&1)<<3;
    float acc[8][8];
    #pragma unroll
    for(int i=0;i<8;i++)
        #pragma unroll
        for(int j=0;j<8;j++) acc[i][j]=0.f;
    for (int k0=0;k0<K;k0+=16){
        int gm = bm+lm;
        #pragma unroll
        for(int h=0;h<2;h++){
            int kk = lk + 4*h;
            float4 av = (gm < M) ? *(const float4*)(g_Dec + (size_t)gm*K + k0 + kk)
                                 : make_float4(0.f,0.f,0.f,0.f);
            sA[kk+0][lm]=av.x; sA[kk+1][lm]=av.y; sA[kk+2][lm]=av.z; sA[kk+3][lm]=av.w;
            float4 bv = *(const float4*)(B + (size_t)(bn+lm)*K + k0 + kk);
            sB[kk+0][lm]=bv.x; sB[kk+1][lm]=bv.y; sB[kk+2][lm]=bv.z; sB[kk+3][lm]=bv.w;
        }
        __syncthreads();
        #pragma unroll
        for(int kk=0;kk<16;kk++){
            float4 a0 = *(const float4*)&sA[kk][tm];
            float4 a1 = *(const float4*)&sA[kk][tm+4];
            float4 b0 = *(const float4*)&sB[kk][tn];
            float4 b1 = *(const float4*)&sB[kk][tn+4];
            float aa[8]={a0.x,a0.y,a0.z,a0.w,a1.x,a1.y,a1.z,a1.w};
            float bb[8]={b0.x,b0.y,b0.z,b0.w,b1.x,b1.y,b1.z,b1.w};
            #pragma unroll
            for(int i=0;i<8;i++)
                #pragma unroll
                for(int j=0;j<8;j++) acc[i][j] += aa[i]*bb[j];
        }
        __syncthreads();
    }
    #pragma unroll
    for(int i=0;i<8;i++){
        int m = bm+tm+i;
        if (m < M){
            int t = m >> 5, b = m & 31;
            float* p = out + (size_t)b*(TSTEPS*VOC) + (size_t)t*VOC + bn + tn;
            float4 v0, v1;
            int n = bn+tn;
            v0.x = acc[i][0]+bout[n+0]; v0.y = acc[i][1]+bout[n+1];
            v0.z = acc[i][2]+bout[n+2]; v0.w = acc[i][3]+bout[n+3];
            v1.x = acc[i][4]+bout[n+4]; v1.y = acc[i][5]+bout[n+5];
            v1.z = acc[i][6]+bout[n+6]; v1.w = acc[i][7]+bout[n+7];
            *(float4*)p       = v0;
            *(float4*)(p + 4) = v1;
        }
    }
}

// ---------------- launch ------------------------------------------------------
extern "C" void kernel_launch(void* const* d_in, const int* in_sizes, int n_in,
                              void* d_out, int out_size){
    const int*   tgt  = (const int*)  d_in[0];
    const float* h0   = (const float*)d_in[1];
    const float* c0   = (const float*)d_in[2];
    const float* enc  = (const float*)d_in[3];
    const float* emb  = (const float*)d_in[4];
    const float* Wih  = (const float*)d_in[5];
    const float* Whh  = (const float*)d_in[6];
    const float* bih  = (const float*)d_in[7];
    const float* bhh  = (const float*)d_in[8];
    const float* Ww   = (const float*)d_in[9];
    const float* bw   = (const float*)d_in[10];
    const float* Wout = (const float*)d_in[11];
    const float* bout = (const float*)d_in[12];
    float* out = (float*)d_out;

    k_init <<<128, 256>>>(h0, c0);
    k_embed<<<MROWS, 128>>>(tgt, emb);
    k_xp   <<<dim3(GATES/64, (MROWS+63)/64), 256>>>(Wih, bih, bhh);

    k_loop <<<NCTA, 256>>>(enc, Whh, Ww);

    k_tanh<<<(MROWS*HID)/256, 256>>>(bw);
    k_out <<<dim3(VOC/128, (MROWS+127)/128), 256>>>(Wout, bout, out);
}

// round 5
// speedup vs baseline: 1.5766x; 1.5766x over previous
#include <cuda_runtime.h>
#include <cuda_bf16.h>
#include <math.h>

// Problem dims
#define TSTEPS 63
#define BATCH  32
#define SEQ    64
#define HID    1024
#define EMB    512
#define VOC    32000
#define GATES  4096
#define HC     2048
#define MROWS  (TSTEPS*BATCH)   // 2016

// ---------------- scratch (static device globals; no runtime alloc) -------------
__device__ float g_Emb [MROWS*EMB];
__device__ float g_XP  [MROWS*GATES];
__device__ float g_h   [BATCH*HID];
__device__ float g_c   [BATCH*HID];
__device__ float g_hcat[BATCH*HC];
__device__ float g_gpart[4][BATCH*GATES];
__device__ float g_dpart[8][MROWS*HID];
__device__ __nv_bfloat16 g_DecHi [MROWS*HID];
__device__ __nv_bfloat16 g_DecLo [MROWS*HID];
__device__ __nv_bfloat16 g_WoutHi[(size_t)VOC*HID];
__device__ __nv_bfloat16 g_WoutLo[(size_t)VOC*HID];

// ---------------- init: copy h0/c0 -------------------------------------------
__global__ void k_init(const float* __restrict__ h0, const float* __restrict__ c0){
    int i = blockIdx.x*blockDim.x + threadIdx.x;
    if (i < BATCH*HID){ g_h[i] = h0[i]; g_c[i] = c0[i]; }
}

// ---------------- embedding gather -------------------------------------------
__global__ void k_embed(const int* __restrict__ tgt, const float* __restrict__ emb){
    int r = blockIdx.x;              // 0..2015
    int t = r >> 5, b = r & 31;
    int tok = tgt[b*64 + t];
    const float4* src = (const float4*)(emb + (size_t)tok*EMB);
    float4*       dst = (float4*)(g_Emb + (size_t)r*EMB);
    dst[threadIdx.x] = src[threadIdx.x];
}

// ---------------- W_out fp32 -> bf16 hi/lo ------------------------------------
__global__ void k_cvtW(const float* __restrict__ W){
    size_t i = (size_t)blockIdx.x*blockDim.x + threadIdx.x;   // over 8,192,000 float4
    float4 v = ((const float4*)W)[i];
    __nv_bfloat16 h0 = __float2bfloat16(v.x);
    __nv_bfloat16 h1 = __float2bfloat16(v.y);
    __nv_bfloat16 h2 = __float2bfloat16(v.z);
    __nv_bfloat16 h3 = __float2bfloat16(v.w);
    __nv_bfloat16 l0 = __float2bfloat16(v.x - __bfloat162float(h0));
    __nv_bfloat16 l1 = __float2bfloat16(v.y - __bfloat162float(h1));
    __nv_bfloat16 l2 = __float2bfloat16(v.z - __bfloat162float(h2));
    __nv_bfloat16 l3 = __float2bfloat16(v.w - __bfloat162float(h3));
    __nv_bfloat162* Hi = (__nv_bfloat162*)g_WoutHi;
    __nv_bfloat162* Lo = (__nv_bfloat162*)g_WoutLo;
    Hi[2*i+0] = __nv_bfloat162(h0,h1);
    Hi[2*i+1] = __nv_bfloat162(h2,h3);
    Lo[2*i+0] = __nv_bfloat162(l0,l1);
    Lo[2*i+1] = __nv_bfloat162(l2,l3);
}

// ---------------- XP = Emb @ W_ih^T + b_ih + b_hh  (2016 x 4096, K=512) ------
__global__ void k_xp(const float* __restrict__ B,
                     const float* __restrict__ bih, const float* __restrict__ bhh){
    const int M = MROWS, N = GATES, K = EMB;
    __shared__ float sA[16][68];
    __shared__ float sB[16][68];
    int bm = blockIdx.y*64, bn = blockIdx.x*64;
    int tid = threadIdx.x;
    int tm = (tid>>4)<<2, tn = (tid&15)<<2;
    int lm = tid>>2, lk = (tid&3)<<2;
    float acc[4][4];
    #pragma unroll
    for(int i=0;i<4;i++){ acc[i][0]=0.f; acc[i][1]=0.f; acc[i][2]=0.f; acc[i][3]=0.f; }
    for (int k0=0;k0<K;k0+=16){
        int gm = bm+lm;
        float4 av = (gm < M) ? *(const float4*)(g_Emb + (size_t)gm*K + k0 + lk)
                             : make_float4(0.f,0.f,0.f,0.f);
        sA[lk+0][lm]=av.x; sA[lk+1][lm]=av.y; sA[lk+2][lm]=av.z; sA[lk+3][lm]=av.w;
        float4 bv = *(const float4*)(B + (size_t)(bn+lm)*K + k0 + lk);
        sB[lk+0][lm]=bv.x; sB[lk+1][lm]=bv.y; sB[lk+2][lm]=bv.z; sB[lk+3][lm]=bv.w;
        __syncthreads();
        #pragma unroll
        for(int kk=0;kk<16;kk++){
            float4 a = *(const float4*)&sA[kk][tm];
            float4 b = *(const float4*)&sB[kk][tn];
            float aa[4]={a.x,a.y,a.z,a.w}, bb[4]={b.x,b.y,b.z,b.w};
            #pragma unroll
            for(int i=0;i<4;i++)
                #pragma unroll
                for(int j=0;j<4;j++) acc[i][j] += aa[i]*bb[j];
        }
        __syncthreads();
    }
    #pragma unroll
    for(int i=0;i<4;i++){
        int m = bm+tm+i;
        if (m < M){
            #pragma unroll
            for(int j=0;j<4;j++){
                int n = bn+tn+j;
                g_XP[(size_t)m*N + n] = acc[i][j] + bih[n] + bhh[n];
            }
        }
    }
}

// ---------------- gates partial: g_gpart[slice] = h @ W_hh^T (K-slice) -------
__global__ void k_gates(const float* __restrict__ B){
    const int N = GATES, K = HID;
    __shared__ float sA[16][36];
    __shared__ float sB[16][68];
    int bn = blockIdx.x*64;
    int Koff = blockIdx.y*256;
    int tid = threadIdx.x;               // 128
    int tm = (tid>>4)<<2, tn = (tid&15)<<2;
    int lm = tid>>2, lk = (tid&3)<<2;
    float acc[4][4];
    #pragma unroll
    for(int i=0;i<4;i++){ acc[i][0]=0.f; acc[i][1]=0.f; acc[i][2]=0.f; acc[i][3]=0.f; }
    for (int k0=0;k0<256;k0+=16){
        float4 av = *(const float4*)(g_h + (size_t)lm*K + Koff + k0 + lk);
        sA[lk+0][lm]=av.x; sA[lk+1][lm]=av.y; sA[lk+2][lm]=av.z; sA[lk+3][lm]=av.w;
        #pragma unroll
        for (int r=0;r<2;r++){
            int n = lm + 32*r;
            float4 bv = *(const float4*)(B + (size_t)(bn+n)*K + Koff + k0 + lk);
            sB[lk+0][n]=bv.x; sB[lk+1][n]=bv.y; sB[lk+2][n]=bv.z; sB[lk+3][n]=bv.w;
        }
        __syncthreads();
        #pragma unroll
        for(int kk=0;kk<16;kk++){
            float4 a = *(const float4*)&sA[kk][tm];
            float4 b = *(const float4*)&sB[kk][tn];
            float aa[4]={a.x,a.y,a.z,a.w}, bb[4]={b.x,b.y,b.z,b.w};
            #pragma unroll
            for(int i=0;i<4;i++)
                #pragma unroll
                for(int j=0;j<4;j++) acc[i][j] += aa[i]*bb[j];
        }
        __syncthreads();
    }
    float* dst = g_gpart[blockIdx.y];
    #pragma unroll
    for(int i=0;i<4;i++)
        #pragma unroll
        for(int j=0;j<4;j++)
            dst[(size_t)(tm+i)*N + bn+tn+j] = acc[i][j];
}

// ---------------- LSTM cell ----------------------------------------------------
__global__ void k_cell(int t){
    int idx = blockIdx.x*blockDim.x + threadIdx.x;   // 32768
    int b = idx >> 10, j = idx & 1023;
    size_t base = (size_t)b*GATES;
    const float* xp = g_XP + ((size_t)t*BATCH + b)*GATES;
    float gi = xp[j], gf = xp[1024+j], gg = xp[2048+j], go = xp[3072+j];
    #pragma unroll
    for(int s=0;s<4;s++){
        const float* gp = g_gpart[s] + base;
        gi += gp[j]; gf += gp[1024+j]; gg += gp[2048+j]; go += gp[3072+j];
    }
    float i_ = 1.f/(1.f+expf(-gi));
    float f_ = 1.f/(1.f+expf(-gf));
    float g_ = tanhf(gg);
    float o_ = 1.f/(1.f+expf(-go));
    float c  = f_*g_c[idx] + i_*g_;
    g_c[idx] = c;
    float h  = o_*tanhf(c);
    g_h[idx] = h;
    g_hcat[(size_t)b*HC + j] = h;
}

// ---------------- attention ----------------------------------------------------
__global__ void k_attn(const float* __restrict__ enc){
    int b = blockIdx.x, tid = threadIdx.x;   // 256 threads
    __shared__ float sh[HID];
    __shared__ float ss[SEQ];
    for (int i=tid;i<HID;i+=256) sh[i] = g_h[(size_t)b*HID+i];
    __syncthreads();
    int warp = tid>>5, lane = tid&31;
    for (int s=warp; s<SEQ; s+=8){
        const float* e = enc + ((size_t)b*SEQ + s)*HID;
        float acc = 0.f;
        for (int k=lane;k<HID;k+=32) acc += sh[k]*e[k];
        #pragma unroll
        for(int o=16;o;o>>=1) acc += __shfl_xor_sync(0xffffffffu, acc, o);
        if (!lane) ss[s] = acc;
    }
    __syncthreads();
    if (tid == 0){
        float mx = -1e30f;
        for(int s=0;s<SEQ;s++) mx = fmaxf(mx, ss[s]);
        float sum = 0.f;
        for(int s=0;s<SEQ;s++){ float e = expf(ss[s]-mx); ss[s]=e; sum+=e; }
        float inv = 1.f/sum;
        for(int s=0;s<SEQ;s++) ss[s] *= inv;
    }
    __syncthreads();
    int j = tid<<2;
    float c0=0.f,c1=0.f,c2=0.f,c3=0.f;
    for(int s=0;s<SEQ;s++){
        float a = ss[s];
        float4 v = *(const float4*)(enc + ((size_t)b*SEQ+s)*HID + j);
        c0 += a*v.x; c1 += a*v.y; c2 += a*v.z; c3 += a*v.w;
    }
    *(float4*)(g_hcat + (size_t)b*HC + HID + j) = make_float4(c0,c1,c2,c3);
}

// ---------------- dec partial --------------------------------------------------
__global__ void k_dec(const float* __restrict__ B, int t){
    const int N = HID, K = HC;
    __shared__ float sA[16][36];
    __shared__ float sB[16][68];
    int bn = blockIdx.x*64;
    int Koff = blockIdx.y*256;
    int tid = threadIdx.x;               // 128
    int tm = (tid>>4)<<2, tn = (tid&15)<<2;
    int lm = tid>>2, lk = (tid&3)<<2;
    float acc[4][4];
    #pragma unroll
    for(int i=0;i<4;i++){ acc[i][0]=0.f; acc[i][1]=0.f; acc[i][2]=0.f; acc[i][3]=0.f; }
    for (int k0=0;k0<256;k0+=16){
        float4 av = *(const float4*)(g_hcat + (size_t)lm*K + Koff + k0 + lk);
        sA[lk+0][lm]=av.x; sA[lk+1][lm]=av.y; sA[lk+2][lm]=av.z; sA[lk+3][lm]=av.w;
        #pragma unroll
        for (int r=0;r<2;r++){
            int n = lm + 32*r;
            float4 bv = *(const float4*)(B + (size_t)(bn+n)*K + Koff + k0 + lk);
            sB[lk+0][n]=bv.x; sB[lk+1][n]=bv.y; sB[lk+2][n]=bv.z; sB[lk+3][n]=bv.w;
        }
        __syncthreads();
        #pragma unroll
        for(int kk=0;kk<16;kk++){
            float4 a = *(const float4*)&sA[kk][tm];
            float4 b = *(const float4*)&sB[kk][tn];
            float aa[4]={a.x,a.y,a.z,a.w}, bb[4]={b.x,b.y,b.z,b.w};
            #pragma unroll
            for(int i=0;i<4;i++)
                #pragma unroll
                for(int j=0;j<4;j++) acc[i][j] += aa[i]*bb[j];
        }
        __syncthreads();
    }
    float* dst = g_dpart[blockIdx.y] + (size_t)t*BATCH*HID;
    #pragma unroll
    for(int i=0;i<4;i++)
        #pragma unroll
        for(int j=0;j<4;j++)
            dst[(size_t)(tm+i)*N + bn+tn+j] = acc[i][j];
}

// ---------------- tanh reduce -> Dec bf16 hi/lo --------------------------------
__global__ void k_tanh(const float* __restrict__ bw){
    int idx = blockIdx.x*blockDim.x + threadIdx.x;   // 2016*1024
    float s = bw[idx & 1023];
    #pragma unroll
    for(int p=0;p<8;p++) s += g_dpart[p][idx];
    float th = tanhf(s);
    __nv_bfloat16 hi = __float2bfloat16(th);
    __nv_bfloat16 lo = __float2bfloat16(th - __bfloat162float(hi));
    g_DecHi[idx] = hi;
    g_DecLo[idx] = lo;
}

// ---------------- tensor-core output GEMM --------------------------------------
// C[m][n] = sum_k Dec[m][k] * Wout[n][k]; bf16 hi/lo 3-pass, fp32 accum.
__device__ __forceinline__ void ldsm4(unsigned &r0, unsigned &r1, unsigned &r2, unsigned &r3,
                                      unsigned addr){
    asm volatile("ldmatrix.sync.aligned.m8n8.x4.shared.b16 {%0,%1,%2,%3}, [%4];\n"
        : "=r"(r0),"=r"(r1),"=r"(r2),"=r"(r3) : "r"(addr));
}
__device__ __forceinline__ void mma_bf16(float* c, const unsigned* a, const unsigned* b){
    asm volatile("mma.sync.aligned.m16n8k16.row.col.f32.bf16.bf16.f32 "
        "{%0,%1,%2,%3}, {%4,%5,%6,%7}, {%8,%9}, {%0,%1,%2,%3};\n"
        : "+f"(c[0]),"+f"(c[1]),"+f"(c[2]),"+f"(c[3])
        : "r"(a[0]),"r"(a[1]),"r"(a[2]),"r"(a[3]), "r"(b[0]),"r"(b[1]));
}

#define SROW 40   // padded smem row stride in bf16 (80 bytes -> conflict-free ldmatrix)

__global__ void __launch_bounds__(256,1)
k_out_mma(const float* __restrict__ bout, float* __restrict__ out){
    __shared__ __align__(16) __nv_bfloat16 sAh[128*SROW];
    __shared__ __align__(16) __nv_bfloat16 sAl[128*SROW];
    __shared__ __align__(16) __nv_bfloat16 sBh[128*SROW];
    __shared__ __align__(16) __nv_bfloat16 sBl[128*SROW];

    const int bm = blockIdx.y*128, bn = blockIdx.x*128;
    const int tid = threadIdx.x, lane = tid & 31, warp = tid >> 5;
    const int wm = warp & 3, wn = warp >> 2;      // warp tile: rows wm*32, cols wn*64

    float acc[2][8][4];
    #pragma unroll
    for(int i=0;i<2;i++)
        #pragma unroll
        for(int j=0;j<8;j++){ acc[i][j][0]=0.f; acc[i][j][1]=0.f; acc[i][j][2]=0.f; acc[i][j][3]=0.f; }

    // register staging buffers (2 x uint4 per array per thread)
    uint4 rAh[2], rAl[2], rBh[2], rBl[2];
    const uint4 z4 = make_uint4(0u,0u,0u,0u);

    unsigned uAh = (unsigned)__cvta_generic_to_shared(sAh);
    unsigned uAl = (unsigned)__cvta_generic_to_shared(sAl);
    unsigned uBh = (unsigned)__cvta_generic_to_shared(sBh);
    unsigned uBl = (unsigned)__cvta_generic_to_shared(sBl);

    int r0i = (tid*2) >> 2, s0 = (tid*2) & 3;     // i=0: row, seg
    int r1i = (tid*2+1) >> 2, s1 = (tid*2+1) & 3; // i=1

    #define LOADCH(ch) do{                                                        \
        size_t ko = (size_t)(ch)*32;                                              \
        bool ok0 = (bm+r0i) < MROWS, ok1 = (bm+r1i) < MROWS;                      \
        rAh[0] = ok0 ? *(const uint4*)(g_DecHi + (size_t)(bm+r0i)*HID + ko + s0*8) : z4; \
        rAl[0] = ok0 ? *(const uint4*)(g_DecLo + (size_t)(bm+r0i)*HID + ko + s0*8) : z4; \
        rAh[1] = ok1 ? *(const uint4*)(g_DecHi + (size_t)(bm+r1i)*HID + ko + s1*8) : z4; \
        rAl[1] = ok1 ? *(const uint4*)(g_DecLo + (size_t)(bm+r1i)*HID + ko + s1*8) : z4; \
        rBh[0] = *(const uint4*)(g_WoutHi + (size_t)(bn+r0i)*HID + ko + s0*8);    \
        rBl[0] = *(const uint4*)(g_WoutLo + (size_t)(bn+r0i)*HID + ko + s0*8);    \
        rBh[1] = *(const uint4*)(g_WoutHi + (size_t)(bn+r1i)*HID + ko + s1*8);    \
        rBl[1] = *(const uint4*)(g_WoutLo + (size_t)(bn+r1i)*HID + ko + s1*8);    \
    }while(0)

    LOADCH(0);

    for (int ch = 0; ch < 32; ch++){
        __syncthreads();
        *(uint4*)(sAh + r0i*SROW + s0*8) = rAh[0];
        *(uint4*)(sAl + r0i*SROW + s0*8) = rAl[0];
        *(uint4*)(sBh + r0i*SROW + s0*8) = rBh[0];
        *(uint4*)(sBl + r0i*SROW + s0*8) = rBl[0];
        *(uint4*)(sAh + r1i*SROW + s1*8) = rAh[1];
        *(uint4*)(sAl + r1i*SROW + s1*8) = rAl[1];
        *(uint4*)(sBh + r1i*SROW + s1*8) = rBh[1];
        *(uint4*)(sBl + r1i*SROW + s1*8) = rBl[1];
        __syncthreads();
        if (ch+1 < 32) LOADCH(ch+1);

        #pragma unroll
        for (int ks = 0; ks < 2; ks++){
            unsigned ah[2][4], al[2][4], bh[8][2], bl[8][2];
            // A fragments: lanes 0-7 rows r..r+7 kLo | 8-15 rows+8 kLo | 16-23 rows kHi | 24-31 rows+8 kHi
            int arow = wm*32 + (lane & 15);
            int acol = ks*16 + ((lane & 16) ? 8 : 0);
            #pragma unroll
            for (int mt = 0; mt < 2; mt++){
                unsigned off = (unsigned)((arow + mt*16)*SROW + acol) * 2u;
                ldsm4(ah[mt][0], ah[mt][1], ah[mt][2], ah[mt][3], uAh + off);
                ldsm4(al[mt][0], al[mt][1], al[mt][2], al[mt][3], uAl + off);
            }
            // B fragments: lanes 0-7 n..n+7 kLo | 8-15 same n kHi | 16-23 n+8 kLo | 24-31 n+8 kHi
            int brow = wn*64 + (lane & 7) + ((lane & 16) ? 8 : 0);
            int bcol = ks*16 + ((lane & 8) ? 8 : 0);
            #pragma unroll
            for (int p = 0; p < 4; p++){
                unsigned off = (unsigned)((brow + p*16)*SROW + bcol) * 2u;
                ldsm4(bh[2*p][0], bh[2*p][1], bh[2*p+1][0], bh[2*p+1][1], uBh + off);
                ldsm4(bl[2*p][0], bl[2*p][1], bl[2*p+1][0], bl[2*p+1][1], uBl + off);
            }
            #pragma unroll
            for (int mt = 0; mt < 2; mt++)
                #pragma unroll
                for (int nt = 0; nt < 8; nt++){
                    mma_bf16(acc[mt][nt], ah[mt], bh[nt]);   // hi*hi
                    mma_bf16(acc[mt][nt], ah[mt], bl[nt]);   // hi*lo
                    mma_bf16(acc[mt][nt], al[mt], bh[nt]);   // lo*hi
                }
        }
    }

    // epilogue: scatter (t,b), add bias
    #pragma unroll
    for (int mt = 0; mt < 2; mt++){
        int m0 = bm + wm*32 + mt*16 + (lane >> 2);
        int m1 = m0 + 8;
        #pragma unroll
        for (int nt = 0; nt < 8; nt++){
            int n = bn + wn*64 + nt*8 + (lane & 3)*2;
            float b0 = bout[n], b1 = bout[n+1];
            if (m0 < MROWS){
                int t = m0 >> 5, b = m0 & 31;
                float2 v = make_float2(acc[mt][nt][0] + b0, acc[mt][nt][1] + b1);
                *(float2*)(out + (size_t)b*(TSTEPS*VOC) + (size_t)t*VOC + n) = v;
            }
            if (m1 < MROWS){
                int t = m1 >> 5, b = m1 & 31;
                float2 v = make_float2(acc[mt][nt][2] + b0, acc[mt][nt][3] + b1);
                *(float2*)(out + (size_t)b*(TSTEPS*VOC) + (size_t)t*VOC + n) = v;
            }
        }
    }
    #undef LOADCH
}

// ---------------- launch ------------------------------------------------------
extern "C" void kernel_launch(void* const* d_in, const int* in_sizes, int n_in,
                              void* d_out, int out_size){
    const int*   tgt  = (const int*)  d_in[0];
    const float* h0   = (const float*)d_in[1];
    const float* c0   = (const float*)d_in[2];
    const float* enc  = (const float*)d_in[3];
    const float* emb  = (const float*)d_in[4];
    const float* Wih  = (const float*)d_in[5];
    const float* Whh  = (const float*)d_in[6];
    const float* bih  = (const float*)d_in[7];
    const float* bhh  = (const float*)d_in[8];
    const float* Ww   = (const float*)d_in[9];
    const float* bw   = (const float*)d_in[10];
    const float* Wout = (const float*)d_in[11];
    const float* bout = (const float*)d_in[12];
    float* out = (float*)d_out;

    k_init <<<128, 256>>>(h0, c0);
    k_embed<<<MROWS, 128>>>(tgt, emb);
    k_cvtW <<<((size_t)VOC*HID/4)/256, 256>>>(Wout);
    k_xp   <<<dim3(GATES/64, (MROWS+63)/64), 256>>>(Wih, bih, bhh);

    for (int t = 0; t < TSTEPS; t++){
        k_gates<<<dim3(GATES/64, 4), 128>>>(Whh);
        k_cell <<<128, 256>>>(t);
        k_attn <<<BATCH, 256>>>(enc);
        k_dec  <<<dim3(HID/64, 8), 128>>>(Ww, t);
    }

    k_tanh<<<(MROWS*HID)/256, 256>>>(bw);
    k_out_mma<<<dim3(VOC/128, (MROWS+127)/128), 256>>>(bout, out);
}

// round 7
// speedup vs baseline: 1.8181x; 1.1532x over previous
#include <cuda_runtime.h>
#include <cuda_bf16.h>
#include <math.h>

// Problem dims
#define TSTEPS 63
#define BATCH  32
#define SEQ    64
#define HID    1024
#define EMB    512
#define VOC    32000
#define GATES  4096
#define HC     2048
#define MROWS  (TSTEPS*BATCH)   // 2016

// ---------------- scratch (static device globals; no runtime alloc) -------------
__device__ float g_Emb [MROWS*EMB];
__device__ float g_XP  [MROWS*GATES];
__device__ float g_h   [BATCH*HID];
__device__ float g_c   [BATCH*HID];
__device__ float g_hcat[BATCH*HC];
__device__ float g_scores[BATCH*SEQ];
__device__ float g_gpart[8][BATCH*GATES];
__device__ float g_dpart[16][MROWS*HID];
__device__ __nv_bfloat16 g_DecHi [MROWS*HID];
__device__ __nv_bfloat16 g_DecLo [MROWS*HID];
__device__ __nv_bfloat16 g_WoutHi[(size_t)VOC*HID];
__device__ __nv_bfloat16 g_WoutLo[(size_t)VOC*HID];

// ---------------- init: copy h0/c0 -------------------------------------------
__global__ void k_init(const float* __restrict__ h0, const float* __restrict__ c0){
    int i = blockIdx.x*blockDim.x + threadIdx.x;
    if (i < BATCH*HID){ g_h[i] = h0[i]; g_c[i] = c0[i]; }
}

// ---------------- embedding gather -------------------------------------------
__global__ void k_embed(const int* __restrict__ tgt, const float* __restrict__ emb){
    int r = blockIdx.x;              // 0..2015
    int t = r >> 5, b = r & 31;
    int tok = tgt[b*64 + t];
    const float4* src = (const float4*)(emb + (size_t)tok*EMB);
    float4*       dst = (float4*)(g_Emb + (size_t)r*EMB);
    dst[threadIdx.x] = src[threadIdx.x];
}

// ---------------- W_out fp32 -> bf16 hi/lo ------------------------------------
__global__ void k_cvtW(const float* __restrict__ W){
    size_t i = (size_t)blockIdx.x*blockDim.x + threadIdx.x;   // over 8,192,000 float4
    float4 v = ((const float4*)W)[i];
    __nv_bfloat16 h0 = __float2bfloat16(v.x);
    __nv_bfloat16 h1 = __float2bfloat16(v.y);
    __nv_bfloat16 h2 = __float2bfloat16(v.z);
    __nv_bfloat16 h3 = __float2bfloat16(v.w);
    __nv_bfloat16 l0 = __float2bfloat16(v.x - __bfloat162float(h0));
    __nv_bfloat16 l1 = __float2bfloat16(v.y - __bfloat162float(h1));
    __nv_bfloat16 l2 = __float2bfloat16(v.z - __bfloat162float(h2));
    __nv_bfloat16 l3 = __float2bfloat16(v.w - __bfloat162float(h3));
    __nv_bfloat162* Hi = (__nv_bfloat162*)g_WoutHi;
    __nv_bfloat162* Lo = (__nv_bfloat162*)g_WoutLo;
    Hi[2*i+0] = __nv_bfloat162(h0,h1);
    Hi[2*i+1] = __nv_bfloat162(h2,h3);
    Lo[2*i+0] = __nv_bfloat162(l0,l1);
    Lo[2*i+1] = __nv_bfloat162(l2,l3);
}

// ---------------- XP = Emb @ W_ih^T + b_ih + b_hh  (2016 x 4096, K=512) ------
__global__ void k_xp(const float* __restrict__ B,
                     const float* __restrict__ bih, const float* __restrict__ bhh){
    const int M = MROWS, N = GATES, K = EMB;
    __shared__ float sA[16][68];
    __shared__ float sB[16][68];
    int bm = blockIdx.y*64, bn = blockIdx.x*64;
    int tid = threadIdx.x;
    int tm = (tid>>4)<<2, tn = (tid&15)<<2;
    int lm = tid>>2, lk = (tid&3)<<2;
    float acc[4][4];
    #pragma unroll
    for(int i=0;i<4;i++){ acc[i][0]=0.f; acc[i][1]=0.f; acc[i][2]=0.f; acc[i][3]=0.f; }
    for (int k0=0;k0<K;k0+=16){
        int gm = bm+lm;
        float4 av = (gm < M) ? *(const float4*)(g_Emb + (size_t)gm*K + k0 + lk)
                             : make_float4(0.f,0.f,0.f,0.f);
        sA[lk+0][lm]=av.x; sA[lk+1][lm]=av.y; sA[lk+2][lm]=av.z; sA[lk+3][lm]=av.w;
        float4 bv = *(const float4*)(B + (size_t)(bn+lm)*K + k0 + lk);
        sB[lk+0][lm]=bv.x; sB[lk+1][lm]=bv.y; sB[lk+2][lm]=bv.z; sB[lk+3][lm]=bv.w;
        __syncthreads();
        #pragma unroll
        for(int kk=0;kk<16;kk++){
            float4 a = *(const float4*)&sA[kk][tm];
            float4 b = *(const float4*)&sB[kk][tn];
            float aa[4]={a.x,a.y,a.z,a.w}, bb[4]={b.x,b.y,b.z,b.w};
            #pragma unroll
            for(int i=0;i<4;i++)
                #pragma unroll
                for(int j=0;j<4;j++) acc[i][j] += aa[i]*bb[j];
        }
        __syncthreads();
    }
    #pragma unroll
    for(int i=0;i<4;i++){
        int m = bm+tm+i;
        if (m < M){
            #pragma unroll
            for(int j=0;j<4;j++){
                int n = bn+tn+j;
                g_XP[(size_t)m*N + n] = acc[i][j] + bih[n] + bhh[n];
            }
        }
    }
}

// ---------------- gates partial: g_gpart[slice] = h @ W_hh^T (K-slice 128) ----
__global__ void k_gates(const float* __restrict__ B){
    const int N = GATES, K = HID;
    __shared__ float sA[16][36];
    __shared__ float sB[16][68];
    int bn = blockIdx.x*64;
    int Koff = blockIdx.y*128;
    int tid = threadIdx.x;               // 128
    int tm = (tid>>4)<<2, tn = (tid&15)<<2;
    int lm = tid>>2, lk = (tid&3)<<2;
    float acc[4][4];
    #pragma unroll
    for(int i=0;i<4;i++){ acc[i][0]=0.f; acc[i][1]=0.f; acc[i][2]=0.f; acc[i][3]=0.f; }
    for (int k0=0;k0<128;k0+=16){
        float4 av = *(const float4*)(g_h + (size_t)lm*K + Koff + k0 + lk);
        sA[lk+0][lm]=av.x; sA[lk+1][lm]=av.y; sA[lk+2][lm]=av.z; sA[lk+3][lm]=av.w;
        #pragma unroll
        for (int r=0;r<2;r++){
            int n = lm + 32*r;
            float4 bv = *(const float4*)(B + (size_t)(bn+n)*K + Koff + k0 + lk);
            sB[lk+0][n]=bv.x; sB[lk+1][n]=bv.y; sB[lk+2][n]=bv.z; sB[lk+3][n]=bv.w;
        }
        __syncthreads();
        #pragma unroll
        for(int kk=0;kk<16;kk++){
            float4 a = *(const float4*)&sA[kk][tm];
            float4 b = *(const float4*)&sB[kk][tn];
            float aa[4]={a.x,a.y,a.z,a.w}, bb[4]={b.x,b.y,b.z,b.w};
            #pragma unroll
            for(int i=0;i<4;i++)
                #pragma unroll
                for(int j=0;j<4;j++) acc[i][j] += aa[i]*bb[j];
        }
        __syncthreads();
    }
    float* dst = g_gpart[blockIdx.y];
    #pragma unroll
    for(int i=0;i<4;i++)
        #pragma unroll
        for(int j=0;j<4;j++)
            dst[(size_t)(tm+i)*N + bn+tn+j] = acc[i][j];
}

// ---------------- fused LSTM cell + attention scores (one CTA per batch) ------
__global__ void __launch_bounds__(1024,1)
k_cellscore(const float* __restrict__ enc, int t){
    __shared__ float sh[HID];
    int b = blockIdx.x, j = threadIdx.x;       // j = 0..1023
    size_t gbase = (size_t)b*GATES;
    const float* xp = g_XP + ((size_t)t*BATCH + b)*GATES;
    float gi = xp[j], gf = xp[1024+j], gg = xp[2048+j], go = xp[3072+j];
    #pragma unroll
    for(int s=0;s<8;s++){
        const float* gp = g_gpart[s] + gbase;
        gi += gp[j]; gf += gp[1024+j]; gg += gp[2048+j]; go += gp[3072+j];
    }
    float i_ = 1.f/(1.f+expf(-gi));
    float f_ = 1.f/(1.f+expf(-gf));
    float g_ = tanhf(gg);
    float o_ = 1.f/(1.f+expf(-go));
    int idx  = b*HID + j;
    float c  = f_*g_c[idx] + i_*g_;
    g_c[idx] = c;
    float h  = o_*tanhf(c);
    g_h[idx] = h;
    g_hcat[(size_t)b*HC + j] = h;
    sh[j] = h;
    __syncthreads();
    // scores: 32 warps, warp w handles s = w, w+32
    int warp = j>>5, lane = j&31;
    for (int s=warp; s<SEQ; s+=32){
        const float* e = enc + ((size_t)b*SEQ + s)*HID;
        float acc = 0.f;
        #pragma unroll 8
        for (int k=lane;k<HID;k+=32) acc += sh[k]*e[k];
        #pragma unroll
        for(int o=16;o;o>>=1) acc += __shfl_xor_sync(0xffffffffu, acc, o);
        if (!lane) g_scores[b*SEQ + s] = acc;
    }
}

// ---------------- softmax + context: grid (8 chunks, 32 batches), 128 thr -----
__global__ void k_ctx(const float* __restrict__ enc){
    __shared__ float ss[SEQ];
    int g = blockIdx.x, b = blockIdx.y, tid = threadIdx.x;   // 128 threads
    if (tid < SEQ) ss[tid] = g_scores[b*SEQ + tid];
    __syncthreads();
    if (tid == 0){
        float mx = -1e30f;
        for(int s=0;s<SEQ;s++) mx = fmaxf(mx, ss[s]);
        float sum = 0.f;
        for(int s=0;s<SEQ;s++){ float e = expf(ss[s]-mx); ss[s]=e; sum+=e; }
        float inv = 1.f/sum;
        for(int s=0;s<SEQ;s++) ss[s] *= inv;
    }
    __syncthreads();
    int col = g*128 + tid;
    const float* e = enc + (size_t)b*SEQ*HID + col;
    float ctx = 0.f;
    #pragma unroll 8
    for (int s=0;s<SEQ;s++) ctx += ss[s]*e[(size_t)s*HID];
    g_hcat[(size_t)b*HC + HID + col] = ctx;
}

// ---------------- dec partial: g_dpart[Ks][t] (K-slice 128) --------------------
__global__ void k_dec(const float* __restrict__ B, int t){
    const int N = HID, K = HC;
    __shared__ float sA[16][36];
    __shared__ float sB[16][68];
    int bn = blockIdx.x*64;
    int Koff = blockIdx.y*128;
    int tid = threadIdx.x;               // 128
    int tm = (tid>>4)<<2, tn = (tid&15)<<2;
    int lm = tid>>2, lk = (tid&3)<<2;
    float acc[4][4];
    #pragma unroll
    for(int i=0;i<4;i++){ acc[i][0]=0.f; acc[i][1]=0.f; acc[i][2]=0.f; acc[i][3]=0.f; }
    for (int k0=0;k0<128;k0+=16){
        float4 av = *(const float4*)(g_hcat + (size_t)lm*K + Koff + k0 + lk);
        sA[lk+0][lm]=av.x; sA[lk+1][lm]=av.y; sA[lk+2][lm]=av.z; sA[lk+3][lm]=av.w;
        #pragma unroll
        for (int r=0;r<2;r++){
            int n = lm + 32*r;
            float4 bv = *(const float4*)(B + (size_t)(bn+n)*K + Koff + k0 + lk);
            sB[lk+0][n]=bv.x; sB[lk+1][n]=bv.y; sB[lk+2][n]=bv.z; sB[lk+3][n]=bv.w;
        }
        __syncthreads();
        #pragma unroll
        for(int kk=0;kk<16;kk++){
            float4 a = *(const float4*)&sA[kk][tm];
            float4 b = *(const float4*)&sB[kk][tn];
            float aa[4]={a.x,a.y,a.z,a.w}, bb[4]={b.x,b.y,b.z,b.w};
            #pragma unroll
            for(int i=0;i<4;i++)
                #pragma unroll
                for(int j=0;j<4;j++) acc[i][j] += aa[i]*bb[j];
        }
        __syncthreads();
    }
    float* dst = g_dpart[blockIdx.y] + (size_t)t*BATCH*HID;
    #pragma unroll
    for(int i=0;i<4;i++)
        #pragma unroll
        for(int j=0;j<4;j++)
            dst[(size_t)(tm+i)*N + bn+tn+j] = acc[i][j];
}

// ---------------- tanh reduce (16 slices) -> Dec bf16 hi/lo --------------------
__global__ void k_tanh(const float* __restrict__ bw){
    int idx = blockIdx.x*blockDim.x + threadIdx.x;   // 2016*1024
    float s = bw[idx & 1023];
    #pragma unroll
    for(int p=0;p<16;p++) s += g_dpart[p][idx];
    float th = tanhf(s);
    __nv_bfloat16 hi = __float2bfloat16(th);
    __nv_bfloat16 lo = __float2bfloat16(th - __bfloat162float(hi));
    g_DecHi[idx] = hi;
    g_DecLo[idx] = lo;
}

// ---------------- tensor-core output GEMM --------------------------------------
__device__ __forceinline__ void ldsm4(unsigned &r0, unsigned &r1, unsigned &r2, unsigned &r3,
                                      unsigned addr){
    asm volatile("ldmatrix.sync.aligned.m8n8.x4.shared.b16 {%0,%1,%2,%3}, [%4];\n"
        : "=r"(r0),"=r"(r1),"=r"(r2),"=r"(r3) : "r"(addr));
}
__device__ __forceinline__ void mma_bf16(float* c, const unsigned* a, const unsigned* b){
    asm volatile("mma.sync.aligned.m16n8k16.row.col.f32.bf16.bf16.f32 "
        "{%0,%1,%2,%3}, {%4,%5,%6,%7}, {%8,%9}, {%0,%1,%2,%3};\n"
        : "+f"(c[0]),"+f"(c[1]),"+f"(c[2]),"+f"(c[3])
        : "r"(a[0]),"r"(a[1]),"r"(a[2]),"r"(a[3]), "r"(b[0]),"r"(b[1]));
}

#define SROW 40   // padded smem row stride in bf16 (80 bytes -> conflict-free ldmatrix)

__global__ void __launch_bounds__(256,1)
k_out_mma(const float* __restrict__ bout, float* __restrict__ out){
    __shared__ __align__(16) __nv_bfloat16 sAh[128*SROW];
    __shared__ __align__(16) __nv_bfloat16 sAl[128*SROW];
    __shared__ __align__(16) __nv_bfloat16 sBh[128*SROW];
    __shared__ __align__(16) __nv_bfloat16 sBl[128*SROW];

    const int bm = blockIdx.y*128, bn = blockIdx.x*128;
    const int tid = threadIdx.x, lane = tid & 31, warp = tid >> 5;
    const int wm = warp & 3, wn = warp >> 2;

    float acc[2][8][4];
    #pragma unroll
    for(int i=0;i<2;i++)
        #pragma unroll
        for(int j=0;j<8;j++){ acc[i][j][0]=0.f; acc[i][j][1]=0.f; acc[i][j][2]=0.f; acc[i][j][3]=0.f; }

    uint4 rAh[2], rAl[2], rBh[2], rBl[2];
    const uint4 z4 = make_uint4(0u,0u,0u,0u);

    unsigned uAh = (unsigned)__cvta_generic_to_shared(sAh);
    unsigned uAl = (unsigned)__cvta_generic_to_shared(sAl);
    unsigned uBh = (unsigned)__cvta_generic_to_shared(sBh);
    unsigned uBl = (unsigned)__cvta_generic_to_shared(sBl);

    int r0i = (tid*2) >> 2, s0 = (tid*2) & 3;
    int r1i = (tid*2+1) >> 2, s1 = (tid*2+1) & 3;

    #define LOADCH(ch) do{                                                        \
        size_t ko = (size_t)(ch)*32;                                              \
        bool ok0 = (bm+r0i) < MROWS, ok1 = (bm+r1i) < MROWS;                      \
        rAh[0] = ok0 ? *(const uint4*)(g_DecHi + (size_t)(bm+r0i)*HID + ko + s0*8) : z4; \
        rAl[0] = ok0 ? *(const uint4*)(g_DecLo + (size_t)(bm+r0i)*HID + ko + s0*8) : z4; \
        rAh[1] = ok1 ? *(const uint4*)(g_DecHi + (size_t)(bm+r1i)*HID + ko + s1*8) : z4; \
        rAl[1] = ok1 ? *(const uint4*)(g_DecLo + (size_t)(bm+r1i)*HID + ko + s1*8) : z4; \
        rBh[0] = *(const uint4*)(g_WoutHi + (size_t)(bn+r0i)*HID + ko + s0*8);    \
        rBl[0] = *(const uint4*)(g_WoutLo + (size_t)(bn+r0i)*HID + ko + s0*8);    \
        rBh[1] = *(const uint4*)(g_WoutHi + (size_t)(bn+r1i)*HID + ko + s1*8);    \
        rBl[1] = *(const uint4*)(g_WoutLo + (size_t)(bn+r1i)*HID + ko + s1*8);    \
    }while(0)

    LOADCH(0);

    for (int ch = 0; ch < 32; ch++){
        __syncthreads();
        *(uint4*)(sAh + r0i*SROW + s0*8) = rAh[0];
        *(uint4*)(sAl + r0i*SROW + s0*8) = rAl[0];
        *(uint4*)(sBh + r0i*SROW + s0*8) = rBh[0];
        *(uint4*)(sBl + r0i*SROW + s0*8) = rBl[0];
        *(uint4*)(sAh + r1i*SROW + s1*8) = rAh[1];
        *(uint4*)(sAl + r1i*SROW + s1*8) = rAl[1];
        *(uint4*)(sBh + r1i*SROW + s1*8) = rBh[1];
        *(uint4*)(sBl + r1i*SROW + s1*8) = rBl[1];
        __syncthreads();
        if (ch+1 < 32) LOADCH(ch+1);

        #pragma unroll
        for (int ks = 0; ks < 2; ks++){
            unsigned ah[2][4], al[2][4], bh[8][2], bl[8][2];
            int arow = wm*32 + (lane & 15);
            int acol = ks*16 + ((lane & 16) ? 8 : 0);
            #pragma unroll
            for (int mt = 0; mt < 2; mt++){
                unsigned off = (unsigned)((arow + mt*16)*SROW + acol) * 2u;
                ldsm4(ah[mt][0], ah[mt][1], ah[mt][2], ah[mt][3], uAh + off);
                ldsm4(al[mt][0], al[mt][1], al[mt][2], al[mt][3], uAl + off);
            }
            int brow = wn*64 + (lane & 7) + ((lane & 16) ? 8 : 0);
            int bcol = ks*16 + ((lane & 8) ? 8 : 0);
            #pragma unroll
            for (int p = 0; p < 4; p++){
                unsigned off = (unsigned)((brow + p*16)*SROW + bcol) * 2u;
                ldsm4(bh[2*p][0], bh[2*p][1], bh[2*p+1][0], bh[2*p+1][1], uBh + off);
                ldsm4(bl[2*p][0], bl[2*p][1], bl[2*p+1][0], bl[2*p+1][1], uBl + off);
            }
            #pragma unroll
            for (int mt = 0; mt < 2; mt++)
                #pragma unroll
                for (int nt = 0; nt < 8; nt++){
                    mma_bf16(acc[mt][nt], ah[mt], bh[nt]);
                    mma_bf16(acc[mt][nt], ah[mt], bl[nt]);
                    mma_bf16(acc[mt][nt], al[mt], bh[nt]);
                }
        }
    }

    #pragma unroll
    for (int mt = 0; mt < 2; mt++){
        int m0 = bm + wm*32 + mt*16 + (lane >> 2);
        int m1 = m0 + 8;
        #pragma unroll
        for (int nt = 0; nt < 8; nt++){
            int n = bn + wn*64 + nt*8 + (lane & 3)*2;
            float b0 = bout[n], b1 = bout[n+1];
            if (m0 < MROWS){
                int t = m0 >> 5, b = m0 & 31;
                float2 v = make_float2(acc[mt][nt][0] + b0, acc[mt][nt][1] + b1);
                *(float2*)(out + (size_t)b*(TSTEPS*VOC) + (size_t)t*VOC + n) = v;
            }
            if (m1 < MROWS){
                int t = m1 >> 5, b = m1 & 31;
                float2 v = make_float2(acc[mt][nt][2] + b0, acc[mt][nt][3] + b1);
                *(float2*)(out + (size_t)b*(TSTEPS*VOC) + (size_t)t*VOC + n) = v;
            }
        }
    }
    #undef LOADCH
}

// ---------------- launch ------------------------------------------------------
extern "C" void kernel_launch(void* const* d_in, const int* in_sizes, int n_in,
                              void* d_out, int out_size){
    const int*   tgt  = (const int*)  d_in[0];
    const float* h0   = (const float*)d_in[1];
    const float* c0   = (const float*)d_in[2];
    const float* enc  = (const float*)d_in[3];
    const float* emb  = (const float*)d_in[4];
    const float* Wih  = (const float*)d_in[5];
    const float* Whh  = (const float*)d_in[6];
    const float* bih  = (const float*)d_in[7];
    const float* bhh  = (const float*)d_in[8];
    const float* Ww   = (const float*)d_in[9];
    const float* bw   = (const float*)d_in[10];
    const float* Wout = (const float*)d_in[11];
    const float* bout = (const float*)d_in[12];
    float* out = (float*)d_out;

    k_init <<<128, 256>>>(h0, c0);
    k_embed<<<MROWS, 128>>>(tgt, emb);
    k_cvtW <<<((size_t)VOC*HID/4)/256, 256>>>(Wout);
    k_xp   <<<dim3(GATES/64, (MROWS+63)/64), 256>>>(Wih, bih, bhh);

    for (int t = 0; t < TSTEPS; t++){
        k_gates    <<<dim3(GATES/64, 8), 128>>>(Whh);
        k_cellscore<<<BATCH, 1024>>>(enc, t);
        k_ctx      <<<dim3(8, BATCH), 128>>>(enc);
        k_dec      <<<dim3(HID/64, 16), 128>>>(Ww, t);
    }

    k_tanh<<<(MROWS*HID)/256, 256>>>(bw);
    k_out_mma<<<dim3(VOC/128, (MROWS+127)/128), 256>>>(bout, out);
}

// round 9
// speedup vs baseline: 1.9828x; 1.0906x over previous
#include <cuda_runtime.h>
#include <cuda_bf16.h>
#include <math.h>

// Problem dims
#define TSTEPS 63
#define BATCH  32
#define SEQ    64
#define HID    1024
#define EMB    512
#define VOC    32000
#define GATES  4096
#define HC     2048
#define MROWS  (TSTEPS*BATCH)   // 2016

// ---------------- scratch (static device globals; no runtime alloc) -------------
__device__ float g_Emb [MROWS*EMB];
__device__ float g_XP  [MROWS*GATES];
__device__ float g_h   [BATCH*HID];
__device__ float g_c   [BATCH*HID];
__device__ float g_hcat[BATCH*HC];
__device__ float g_gpart[8][BATCH*GATES];
__device__ float g_dpart[16][MROWS*HID];
__device__ __nv_bfloat16 g_DecHi [MROWS*HID];
__device__ __nv_bfloat16 g_DecLo [MROWS*HID];
__device__ __nv_bfloat16 g_WoutHi[(size_t)VOC*HID];
__device__ __nv_bfloat16 g_WoutLo[(size_t)VOC*HID];

// ---------------- init: copy h0/c0 -------------------------------------------
__global__ void k_init(const float* __restrict__ h0, const float* __restrict__ c0){
    int i = blockIdx.x*blockDim.x + threadIdx.x;
    if (i < BATCH*HID){ g_h[i] = h0[i]; g_c[i] = c0[i]; }
}

// ---------------- embedding gather -------------------------------------------
__global__ void k_embed(const int* __restrict__ tgt, const float* __restrict__ emb){
    int r = blockIdx.x;              // 0..2015
    int t = r >> 5, b = r & 31;
    int tok = tgt[b*64 + t];
    const float4* src = (const float4*)(emb + (size_t)tok*EMB);
    float4*       dst = (float4*)(g_Emb + (size_t)r*EMB);
    dst[threadIdx.x] = src[threadIdx.x];
}

// ---------------- W_out fp32 -> bf16 hi/lo ------------------------------------
__global__ void k_cvtW(const float* __restrict__ W){
    size_t i = (size_t)blockIdx.x*blockDim.x + threadIdx.x;   // over 8,192,000 float4
    float4 v = ((const float4*)W)[i];
    __nv_bfloat16 h0 = __float2bfloat16(v.x);
    __nv_bfloat16 h1 = __float2bfloat16(v.y);
    __nv_bfloat16 h2 = __float2bfloat16(v.z);
    __nv_bfloat16 h3 = __float2bfloat16(v.w);
    __nv_bfloat16 l0 = __float2bfloat16(v.x - __bfloat162float(h0));
    __nv_bfloat16 l1 = __float2bfloat16(v.y - __bfloat162float(h1));
    __nv_bfloat16 l2 = __float2bfloat16(v.z - __bfloat162float(h2));
    __nv_bfloat16 l3 = __float2bfloat16(v.w - __bfloat162float(h3));
    __nv_bfloat162* Hi = (__nv_bfloat162*)g_WoutHi;
    __nv_bfloat162* Lo = (__nv_bfloat162*)g_WoutLo;
    Hi[2*i+0] = __nv_bfloat162(h0,h1);
    Hi[2*i+1] = __nv_bfloat162(h2,h3);
    Lo[2*i+0] = __nv_bfloat162(l0,l1);
    Lo[2*i+1] = __nv_bfloat162(l2,l3);
}

// ---------------- XP = Emb @ W_ih^T + b_ih + b_hh  (2016 x 4096, K=512) ------
__global__ void k_xp(const float* __restrict__ B,
                     const float* __restrict__ bih, const float* __restrict__ bhh){
    const int M = MROWS, N = GATES, K = EMB;
    __shared__ float sA[16][68];
    __shared__ float sB[16][68];
    int bm = blockIdx.y*64, bn = blockIdx.x*64;
    int tid = threadIdx.x;
    int tm = (tid>>4)<<2, tn = (tid&15)<<2;
    int lm = tid>>2, lk = (tid&3)<<2;
    float acc[4][4];
    #pragma unroll
    for(int i=0;i<4;i++){ acc[i][0]=0.f; acc[i][1]=0.f; acc[i][2]=0.f; acc[i][3]=0.f; }
    for (int k0=0;k0<K;k0+=16){
        int gm = bm+lm;
        float4 av = (gm < M) ? *(const float4*)(g_Emb + (size_t)gm*K + k0 + lk)
                             : make_float4(0.f,0.f,0.f,0.f);
        sA[lk+0][lm]=av.x; sA[lk+1][lm]=av.y; sA[lk+2][lm]=av.z; sA[lk+3][lm]=av.w;
        float4 bv = *(const float4*)(B + (size_t)(bn+lm)*K + k0 + lk);
        sB[lk+0][lm]=bv.x; sB[lk+1][lm]=bv.y; sB[lk+2][lm]=bv.z; sB[lk+3][lm]=bv.w;
        __syncthreads();
        #pragma unroll
        for(int kk=0;kk<16;kk++){
            float4 a = *(const float4*)&sA[kk][tm];
            float4 b = *(const float4*)&sB[kk][tn];
            float aa[4]={a.x,a.y,a.z,a.w}, bb[4]={b.x,b.y,b.z,b.w};
            #pragma unroll
            for(int i=0;i<4;i++)
                #pragma unroll
                for(int j=0;j<4;j++) acc[i][j] += aa[i]*bb[j];
        }
        __syncthreads();
    }
    #pragma unroll
    for(int i=0;i<4;i++){
        int m = bm+tm+i;
        if (m < M){
            #pragma unroll
            for(int j=0;j<4;j++){
                int n = bn+tn+j;
                g_XP[(size_t)m*N + n] = acc[i][j] + bih[n] + bhh[n];
            }
        }
    }
}

// ---------------- gates body: g_gpart[slice] = h @ W_hh^T (K-slice 128) -------
__device__ __forceinline__ void gates_body(const float* __restrict__ B, int bn, int Koff,
                                           int tid, float (*sA)[36], float (*sB)[68]){
    const int N = GATES, K = HID;
    int tm = (tid>>4)<<2, tn = (tid&15)<<2;
    int lm = tid>>2, lk = (tid&3)<<2;
    float acc[4][4];
    #pragma unroll
    for(int i=0;i<4;i++){ acc[i][0]=0.f; acc[i][1]=0.f; acc[i][2]=0.f; acc[i][3]=0.f; }
    for (int k0=0;k0<128;k0+=16){
        float4 av = *(const float4*)(g_h + (size_t)lm*K + Koff + k0 + lk);
        sA[lk+0][lm]=av.x; sA[lk+1][lm]=av.y; sA[lk+2][lm]=av.z; sA[lk+3][lm]=av.w;
        #pragma unroll
        for (int r=0;r<2;r++){
            int n = lm + 32*r;
            float4 bv = *(const float4*)(B + (size_t)(bn+n)*K + Koff + k0 + lk);
            sB[lk+0][n]=bv.x; sB[lk+1][n]=bv.y; sB[lk+2][n]=bv.z; sB[lk+3][n]=bv.w;
        }
        __syncthreads();
        #pragma unroll
        for(int kk=0;kk<16;kk++){
            float4 a = *(const float4*)&sA[kk][tm];
            float4 b = *(const float4*)&sB[kk][tn];
            float aa[4]={a.x,a.y,a.z,a.w}, bb[4]={b.x,b.y,b.z,b.w};
            #pragma unroll
            for(int i=0;i<4;i++)
                #pragma unroll
                for(int j=0;j<4;j++) acc[i][j] += aa[i]*bb[j];
        }
        __syncthreads();
    }
    float* dst = g_gpart[Koff >> 7];
    #pragma unroll
    for(int i=0;i<4;i++)
        #pragma unroll
        for(int j=0;j<4;j++)
            dst[(size_t)(tm+i)*N + bn+tn+j] = acc[i][j];
}

__global__ void k_gates(const float* __restrict__ B){
    __shared__ float sA[16][36];
    __shared__ float sB[16][68];
    gates_body(B, blockIdx.x*64, blockIdx.y*128, threadIdx.x, sA, sB);
}

// ---------------- dec body: g_dpart[Ks][t] = hcat @ W_w^T (K-slice 128) -------
__device__ __forceinline__ void dec_body(const float* __restrict__ B, int bn, int Koff,
                                         int tid, int t, float (*sA)[36], float (*sB)[68]){
    const int N = HID, K = HC;
    int tm = (tid>>4)<<2, tn = (tid&15)<<2;
    int lm = tid>>2, lk = (tid&3)<<2;
    float acc[4][4];
    #pragma unroll
    for(int i=0;i<4;i++){ acc[i][0]=0.f; acc[i][1]=0.f; acc[i][2]=0.f; acc[i][3]=0.f; }
    for (int k0=0;k0<128;k0+=16){
        float4 av = *(const float4*)(g_hcat + (size_t)lm*K + Koff + k0 + lk);
        sA[lk+0][lm]=av.x; sA[lk+1][lm]=av.y; sA[lk+2][lm]=av.z; sA[lk+3][lm]=av.w;
        #pragma unroll
        for (int r=0;r<2;r++){
            int n = lm + 32*r;
            float4 bv = *(const float4*)(B + (size_t)(bn+n)*K + Koff + k0 + lk);
            sB[lk+0][n]=bv.x; sB[lk+1][n]=bv.y; sB[lk+2][n]=bv.z; sB[lk+3][n]=bv.w;
        }
        __syncthreads();
        #pragma unroll
        for(int kk=0;kk<16;kk++){
            float4 a = *(const float4*)&sA[kk][tm];
            float4 b = *(const float4*)&sB[kk][tn];
            float aa[4]={a.x,a.y,a.z,a.w}, bb[4]={b.x,b.y,b.z,b.w};
            #pragma unroll
            for(int i=0;i<4;i++)
                #pragma unroll
                for(int j=0;j<4;j++) acc[i][j] += aa[i]*bb[j];
        }
        __syncthreads();
    }
    float* dst = g_dpart[Koff >> 7] + (size_t)t*BATCH*HID;
    #pragma unroll
    for(int i=0;i<4;i++)
        #pragma unroll
        for(int j=0;j<4;j++)
            dst[(size_t)(tm+i)*N + bn+tn+j] = acc[i][j];
}

// ---------------- merged dec(t) + gates(t+1): 768 CTAs ------------------------
__global__ void k_decgates(const float* __restrict__ Ww, const float* __restrict__ Whh,
                           int t){
    __shared__ float sA[16][36];
    __shared__ float sB[16][68];
    int blk = blockIdx.x;
    if (blk < 256){   // dec: 16 N-tiles x 16 K-slices
        dec_body(Ww, (blk & 15)*64, (blk >> 4)*128, threadIdx.x, t, sA, sB);
    } else {          // gates: 64 N-tiles x 8 K-slices
        int g = blk - 256;
        gates_body(Whh, (g & 63)*64, (g >> 6)*128, threadIdx.x, sA, sB);
    }
}

// ---------------- fused LSTM cell + scores + softmax + context -----------------
__global__ void __launch_bounds__(1024,1)
k_cellattn(const float* __restrict__ enc, int t){
    __shared__ float sh[HID];
    __shared__ float ss[SEQ];
    int b = blockIdx.x, j = threadIdx.x;       // j = 0..1023
    size_t gbase = (size_t)b*GATES;
    const float* xp = g_XP + ((size_t)t*BATCH + b)*GATES;
    float gi = xp[j], gf = xp[1024+j], gg = xp[2048+j], go = xp[3072+j];
    #pragma unroll
    for(int s=0;s<8;s++){
        const float* gp = g_gpart[s] + gbase;
        gi += gp[j]; gf += gp[1024+j]; gg += gp[2048+j]; go += gp[3072+j];
    }
    float i_ = 1.f/(1.f+expf(-gi));
    float f_ = 1.f/(1.f+expf(-gf));
    float g_ = tanhf(gg);
    float o_ = 1.f/(1.f+expf(-go));
    int idx  = b*HID + j;
    float c  = f_*g_c[idx] + i_*g_;
    g_c[idx] = c;
    float h  = o_*tanhf(c);
    g_h[idx] = h;
    g_hcat[(size_t)b*HC + j] = h;
    sh[j] = h;
    __syncthreads();
    // scores: 32 warps, warp w handles s = w, w+32
    int warp = j>>5, lane = j&31;
    for (int s=warp; s<SEQ; s+=32){
        const float* e = enc + ((size_t)b*SEQ + s)*HID;
        float acc = 0.f;
        #pragma unroll 8
        for (int k=lane;k<HID;k+=32) acc += sh[k]*e[k];
        #pragma unroll
        for(int o=16;o;o>>=1) acc += __shfl_xor_sync(0xffffffffu, acc, o);
        if (!lane) ss[s] = acc;
    }
    __syncthreads();
    if (j == 0){
        float mx = -1e30f;
        for(int s=0;s<SEQ;s++) mx = fmaxf(mx, ss[s]);
        float sum = 0.f;
        for(int s=0;s<SEQ;s++){ float e = expf(ss[s]-mx); ss[s]=e; sum+=e; }
        float inv = 1.f/sum;
        for(int s=0;s<SEQ;s++) ss[s] *= inv;
    }
    __syncthreads();
    // context: thread j handles hid column j
    const float* e = enc + (size_t)b*SEQ*HID + j;
    float ctx = 0.f;
    #pragma unroll 8
    for (int s=0;s<SEQ;s++) ctx += ss[s]*e[(size_t)s*HID];
    g_hcat[(size_t)b*HC + HID + j] = ctx;
}

// ---------------- tanh reduce (16 slices) -> Dec bf16 hi/lo --------------------
__global__ void k_tanh(const float* __restrict__ bw){
    int idx = blockIdx.x*blockDim.x + threadIdx.x;   // 2016*1024
    float s = bw[idx & 1023];
    #pragma unroll
    for(int p=0;p<16;p++) s += g_dpart[p][idx];
    float th = tanhf(s);
    __nv_bfloat16 hi = __float2bfloat16(th);
    __nv_bfloat16 lo = __float2bfloat16(th - __bfloat162float(hi));
    g_DecHi[idx] = hi;
    g_DecLo[idx] = lo;
}

// ---------------- tensor-core output GEMM --------------------------------------
__device__ __forceinline__ void ldsm4(unsigned &r0, unsigned &r1, unsigned &r2, unsigned &r3,
                                      unsigned addr){
    asm volatile("ldmatrix.sync.aligned.m8n8.x4.shared.b16 {%0,%1,%2,%3}, [%4];\n"
        : "=r"(r0),"=r"(r1),"=r"(r2),"=r"(r3) : "r"(addr));
}
__device__ __forceinline__ void mma_bf16(float* c, const unsigned* a, const unsigned* b){
    asm volatile("mma.sync.aligned.m16n8k16.row.col.f32.bf16.bf16.f32 "
        "{%0,%1,%2,%3}, {%4,%5,%6,%7}, {%8,%9}, {%0,%1,%2,%3};\n"
        : "+f"(c[0]),"+f"(c[1]),"+f"(c[2]),"+f"(c[3])
        : "r"(a[0]),"r"(a[1]),"r"(a[2]),"r"(a[3]), "r"(b[0]),"r"(b[1]));
}

#define SROW 40   // padded smem row stride in bf16 (80 bytes -> conflict-free ldmatrix)

__global__ void __launch_bounds__(256,1)
k_out_mma(const float* __restrict__ bout, float* __restrict__ out){
    __shared__ __align__(16) __nv_bfloat16 sAh[128*SROW];
    __shared__ __align__(16) __nv_bfloat16 sAl[128*SROW];
    __shared__ __align__(16) __nv_bfloat16 sBh[128*SROW];
    __shared__ __align__(16) __nv_bfloat16 sBl[128*SROW];

    const int bm = blockIdx.y*128, bn = blockIdx.x*128;
    const int tid = threadIdx.x, lane = tid & 31, warp = tid >> 5;
    const int wm = warp & 3, wn = warp >> 2;

    float acc[2][8][4];
    #pragma unroll
    for(int i=0;i<2;i++)
        #pragma unroll
        for(int j=0;j<8;j++){ acc[i][j][0]=0.f; acc[i][j][1]=0.f; acc[i][j][2]=0.f; acc[i][j][3]=0.f; }

    uint4 rAh[2], rAl[2], rBh[2], rBl[2];
    const uint4 z4 = make_uint4(0u,0u,0u,0u);

    unsigned uAh = (unsigned)__cvta_generic_to_shared(sAh);
    unsigned uAl = (unsigned)__cvta_generic_to_shared(sAl);
    unsigned uBh = (unsigned)__cvta_generic_to_shared(sBh);
    unsigned uBl = (unsigned)__cvta_generic_to_shared(sBl);

    int r0i = (tid*2) >> 2, s0 = (tid*2) & 3;
    int r1i = (tid*2+1) >> 2, s1 = (tid*2+1) & 3;

    #define LOADCH(ch) do{                                                        \
        size_t ko = (size_t)(ch)*32;                                              \
        bool ok0 = (bm+r0i) < MROWS, ok1 = (bm+r1i) < MROWS;                      \
        rAh[0] = ok0 ? *(const uint4*)(g_DecHi + (size_t)(bm+r0i)*HID + ko + s0*8) : z4; \
        rAl[0] = ok0 ? *(const uint4*)(g_DecLo + (size_t)(bm+r0i)*HID + ko + s0*8) : z4; \
        rAh[1] = ok1 ? *(const uint4*)(g_DecHi + (size_t)(bm+r1i)*HID + ko + s1*8) : z4; \
        rAl[1] = ok1 ? *(const uint4*)(g_DecLo + (size_t)(bm+r1i)*HID + ko + s1*8) : z4; \
        rBh[0] = *(const uint4*)(g_WoutHi + (size_t)(bn+r0i)*HID + ko + s0*8);    \
        rBl[0] = *(const uint4*)(g_WoutLo + (size_t)(bn+r0i)*HID + ko + s0*8);    \
        rBh[1] = *(const uint4*)(g_WoutHi + (size_t)(bn+r1i)*HID + ko + s1*8);    \
        rBl[1] = *(const uint4*)(g_WoutLo + (size_t)(bn+r1i)*HID + ko + s1*8);    \
    }while(0)

    LOADCH(0);

    for (int ch = 0; ch < 32; ch++){
        __syncthreads();
        *(uint4*)(sAh + r0i*SROW + s0*8) = rAh[0];
        *(uint4*)(sAl + r0i*SROW + s0*8) = rAl[0];
        *(uint4*)(sBh + r0i*SROW + s0*8) = rBh[0];
        *(uint4*)(sBl + r0i*SROW + s0*8) = rBl[0];
        *(uint4*)(sAh + r1i*SROW + s1*8) = rAh[1];
        *(uint4*)(sAl + r1i*SROW + s1*8) = rAl[1];
        *(uint4*)(sBh + r1i*SROW + s1*8) = rBh[1];
        *(uint4*)(sBl + r1i*SROW + s1*8) = rBl[1];
        __syncthreads();
        if (ch+1 < 32) LOADCH(ch+1);

        #pragma unroll
        for (int ks = 0; ks < 2; ks++){
            unsigned ah[2][4], al[2][4], bh[8][2], bl[8][2];
            int arow = wm*32 + (lane & 15);
            int acol = ks*16 + ((lane & 16) ? 8 : 0);
            #pragma unroll
            for (int mt = 0; mt < 2; mt++){
                unsigned off = (unsigned)((arow + mt*16)*SROW + acol) * 2u;
                ldsm4(ah[mt][0], ah[mt][1], ah[mt][2], ah[mt][3], uAh + off);
                ldsm4(al[mt][0], al[mt][1], al[mt][2], al[mt][3], uAl + off);
            }
            int brow = wn*64 + (lane & 7) + ((lane & 16) ? 8 : 0);
            int bcol = ks*16 + ((lane & 8) ? 8 : 0);
            #pragma unroll
            for (int p = 0; p < 4; p++){
                unsigned off = (unsigned)((brow + p*16)*SROW + bcol) * 2u;
                ldsm4(bh[2*p][0], bh[2*p][1], bh[2*p+1][0], bh[2*p+1][1], uBh + off);
                ldsm4(bl[2*p][0], bl[2*p][1], bl[2*p+1][0], bl[2*p+1][1], uBl + off);
            }
            #pragma unroll
            for (int mt = 0; mt < 2; mt++)
                #pragma unroll
                for (int nt = 0; nt < 8; nt++){
                    mma_bf16(acc[mt][nt], ah[mt], bh[nt]);
                    mma_bf16(acc[mt][nt], ah[mt], bl[nt]);
                    mma_bf16(acc[mt][nt], al[mt], bh[nt]);
                }
        }
    }

    #pragma unroll
    for (int mt = 0; mt < 2; mt++){
        int m0 = bm + wm*32 + mt*16 + (lane >> 2);
        int m1 = m0 + 8;
        #pragma unroll
        for (int nt = 0; nt < 8; nt++){
            int n = bn + wn*64 + nt*8 + (lane & 3)*2;
            float b0 = bout[n], b1 = bout[n+1];
            if (m0 < MROWS){
                int t = m0 >> 5, b = m0 & 31;
                float2 v = make_float2(acc[mt][nt][0] + b0, acc[mt][nt][1] + b1);
                *(float2*)(out + (size_t)b*(TSTEPS*VOC) + (size_t)t*VOC + n) = v;
            }
            if (m1 < MROWS){
                int t = m1 >> 5, b = m1 & 31;
                float2 v = make_float2(acc[mt][nt][2] + b0, acc[mt][nt][3] + b1);
                *(float2*)(out + (size_t)b*(TSTEPS*VOC) + (size_t)t*VOC + n) = v;
            }
        }
    }
    #undef LOADCH
}

// ---------------- launch ------------------------------------------------------
extern "C" void kernel_launch(void* const* d_in, const int* in_sizes, int n_in,
                              void* d_out, int out_size){
    const int*   tgt  = (const int*)  d_in[0];
    const float* h0   = (const float*)d_in[1];
    const float* c0   = (const float*)d_in[2];
    const float* enc  = (const float*)d_in[3];
    const float* emb  = (const float*)d_in[4];
    const float* Wih  = (const float*)d_in[5];
    const float* Whh  = (const float*)d_in[6];
    const float* bih  = (const float*)d_in[7];
    const float* bhh  = (const float*)d_in[8];
    const float* Ww   = (const float*)d_in[9];
    const float* bw   = (const float*)d_in[10];
    const float* Wout = (const float*)d_in[11];
    const float* bout = (const float*)d_in[12];
    float* out = (float*)d_out;

    k_init <<<128, 256>>>(h0, c0);
    k_embed<<<MROWS, 128>>>(tgt, emb);
    k_cvtW <<<((size_t)VOC*HID/4)/256, 256>>>(Wout);
    k_xp   <<<dim3(GATES/64, (MROWS+63)/64), 256>>>(Wih, bih, bhh);

    k_gates<<<dim3(GATES/64, 8), 128>>>(Whh);   // gates for t=0
    for (int t = 0; t < TSTEPS; t++){
        k_cellattn<<<BATCH, 1024>>>(enc, t);
        k_decgates<<<768, 128>>>(Ww, Whh, t);   // dec(t) + gates(t+1)
    }

    k_tanh<<<(MROWS*HID)/256, 256>>>(bw);
    k_out_mma<<<dim3(VOC/128, (MROWS+127)/128), 256>>>(bout, out);
}

// round 10
// speedup vs baseline: 2.0634x; 1.0407x over previous
#include <cuda_runtime.h>
#include <cuda_bf16.h>
#include <math.h>

// Problem dims
#define TSTEPS 63
#define BATCH  32
#define SEQ    64
#define HID    1024
#define EMB    512
#define VOC    32000
#define GATES  4096
#define HC     2048
#define MROWS  (TSTEPS*BATCH)   // 2016

// ---------------- scratch (static device globals; no runtime alloc) -------------
__device__ float g_XP  [MROWS*GATES];
__device__ float g_h   [BATCH*HID];
__device__ float g_c   [BATCH*HID];
__device__ float g_hcat[BATCH*HC];
__device__ float g_gpart[8][BATCH*GATES];
__device__ float g_dpart[16][MROWS*HID];
__device__ __nv_bfloat16 g_EmbHi [MROWS*EMB];
__device__ __nv_bfloat16 g_EmbLo [MROWS*EMB];
__device__ __nv_bfloat16 g_WihHi [(size_t)GATES*EMB];
__device__ __nv_bfloat16 g_WihLo [(size_t)GATES*EMB];
__device__ __nv_bfloat16 g_DecHi [MROWS*HID];
__device__ __nv_bfloat16 g_DecLo [MROWS*HID];
__device__ __nv_bfloat16 g_WoutHi[(size_t)VOC*HID];
__device__ __nv_bfloat16 g_WoutLo[(size_t)VOC*HID];

// ---------------- init: copy h0/c0 -------------------------------------------
__global__ void k_init(const float* __restrict__ h0, const float* __restrict__ c0){
    int i = blockIdx.x*blockDim.x + threadIdx.x;
    if (i < BATCH*HID){ g_h[i] = h0[i]; g_c[i] = c0[i]; }
}

// ---------------- embedding gather -> bf16 hi/lo ------------------------------
__global__ void k_embed(const int* __restrict__ tgt, const float* __restrict__ emb){
    int r = blockIdx.x;              // 0..2015
    int t = r >> 5, b = r & 31;
    int tok = tgt[b*64 + t];
    float4 v = ((const float4*)(emb + (size_t)tok*EMB))[threadIdx.x];  // 128 thr
    __nv_bfloat16 h0 = __float2bfloat16(v.x);
    __nv_bfloat16 h1 = __float2bfloat16(v.y);
    __nv_bfloat16 h2 = __float2bfloat16(v.z);
    __nv_bfloat16 h3 = __float2bfloat16(v.w);
    __nv_bfloat16 l0 = __float2bfloat16(v.x - __bfloat162float(h0));
    __nv_bfloat16 l1 = __float2bfloat16(v.y - __bfloat162float(h1));
    __nv_bfloat16 l2 = __float2bfloat16(v.z - __bfloat162float(h2));
    __nv_bfloat16 l3 = __float2bfloat16(v.w - __bfloat162float(h3));
    size_t o = (size_t)r*EMB + threadIdx.x*4;
    *(__nv_bfloat162*)(g_EmbHi + o)     = __nv_bfloat162(h0,h1);
    *(__nv_bfloat162*)(g_EmbHi + o + 2) = __nv_bfloat162(h2,h3);
    *(__nv_bfloat162*)(g_EmbLo + o)     = __nv_bfloat162(l0,l1);
    *(__nv_bfloat162*)(g_EmbLo + o + 2) = __nv_bfloat162(l2,l3);
}

// ---------------- W_out fp32 -> bf16 hi/lo (destination named in device code) --
__global__ void k_cvtWout(const float* __restrict__ W){
    size_t i = (size_t)blockIdx.x*blockDim.x + threadIdx.x;   // over float4s
    float4 v = ((const float4*)W)[i];
    __nv_bfloat16 h0 = __float2bfloat16(v.x);
    __nv_bfloat16 h1 = __float2bfloat16(v.y);
    __nv_bfloat16 h2 = __float2bfloat16(v.z);
    __nv_bfloat16 h3 = __float2bfloat16(v.w);
    __nv_bfloat16 l0 = __float2bfloat16(v.x - __bfloat162float(h0));
    __nv_bfloat16 l1 = __float2bfloat16(v.y - __bfloat162float(h1));
    __nv_bfloat16 l2 = __float2bfloat16(v.z - __bfloat162float(h2));
    __nv_bfloat16 l3 = __float2bfloat16(v.w - __bfloat162float(h3));
    __nv_bfloat162* Hi = (__nv_bfloat162*)g_WoutHi;
    __nv_bfloat162* Lo = (__nv_bfloat162*)g_WoutLo;
    Hi[2*i+0] = __nv_bfloat162(h0,h1);
    Hi[2*i+1] = __nv_bfloat162(h2,h3);
    Lo[2*i+0] = __nv_bfloat162(l0,l1);
    Lo[2*i+1] = __nv_bfloat162(l2,l3);
}

// ---------------- W_ih fp32 -> bf16 hi/lo --------------------------------------
__global__ void k_cvtWih(const float* __restrict__ W){
    size_t i = (size_t)blockIdx.x*blockDim.x + threadIdx.x;   // over float4s
    float4 v = ((const float4*)W)[i];
    __nv_bfloat16 h0 = __float2bfloat16(v.x);
    __nv_bfloat16 h1 = __float2bfloat16(v.y);
    __nv_bfloat16 h2 = __float2bfloat16(v.z);
    __nv_bfloat16 h3 = __float2bfloat16(v.w);
    __nv_bfloat16 l0 = __float2bfloat16(v.x - __bfloat162float(h0));
    __nv_bfloat16 l1 = __float2bfloat16(v.y - __bfloat162float(h1));
    __nv_bfloat16 l2 = __float2bfloat16(v.z - __bfloat162float(h2));
    __nv_bfloat16 l3 = __float2bfloat16(v.w - __bfloat162float(h3));
    __nv_bfloat162* Hi = (__nv_bfloat162*)g_WihHi;
    __nv_bfloat162* Lo = (__nv_bfloat162*)g_WihLo;
    Hi[2*i+0] = __nv_bfloat162(h0,h1);
    Hi[2*i+1] = __nv_bfloat162(h2,h3);
    Lo[2*i+0] = __nv_bfloat162(l0,l1);
    Lo[2*i+1] = __nv_bfloat162(l2,l3);
}

// ---------------- tensor-core primitives --------------------------------------
__device__ __forceinline__ void ldsm4(unsigned &r0, unsigned &r1, unsigned &r2, unsigned &r3,
                                      unsigned addr){
    asm volatile("ldmatrix.sync.aligned.m8n8.x4.shared.b16 {%0,%1,%2,%3}, [%4];\n"
        : "=r"(r0),"=r"(r1),"=r"(r2),"=r"(r3) : "r"(addr));
}
__device__ __forceinline__ void mma_bf16(float* c, const unsigned* a, const unsigned* b){
    asm volatile("mma.sync.aligned.m16n8k16.row.col.f32.bf16.bf16.f32 "
        "{%0,%1,%2,%3}, {%4,%5,%6,%7}, {%8,%9}, {%0,%1,%2,%3};\n"
        : "+f"(c[0]),"+f"(c[1]),"+f"(c[2]),"+f"(c[3])
        : "r"(a[0]),"r"(a[1]),"r"(a[2]),"r"(a[3]), "r"(b[0]),"r"(b[1]));
}

#define SROW 40   // padded smem row stride in bf16 (80 bytes -> conflict-free ldmatrix)

// ---------------- XP GEMM (tensor core): Emb(2016x512) @ Wih^T + biases -------
__global__ void __launch_bounds__(256,1)
k_xp_mma(const float* __restrict__ bih, const float* __restrict__ bhh){
    __shared__ __align__(16) __nv_bfloat16 sAh[128*SROW];
    __shared__ __align__(16) __nv_bfloat16 sAl[128*SROW];
    __shared__ __align__(16) __nv_bfloat16 sBh[128*SROW];
    __shared__ __align__(16) __nv_bfloat16 sBl[128*SROW];

    const int bm = blockIdx.y*128, bn = blockIdx.x*128;
    const int tid = threadIdx.x, lane = tid & 31, warp = tid >> 5;
    const int wm = warp & 3, wn = warp >> 2;

    float acc[2][8][4];
    #pragma unroll
    for(int i=0;i<2;i++)
        #pragma unroll
        for(int j=0;j<8;j++){ acc[i][j][0]=0.f; acc[i][j][1]=0.f; acc[i][j][2]=0.f; acc[i][j][3]=0.f; }

    uint4 rAh[2], rAl[2], rBh[2], rBl[2];
    const uint4 z4 = make_uint4(0u,0u,0u,0u);

    unsigned uAh = (unsigned)__cvta_generic_to_shared(sAh);
    unsigned uAl = (unsigned)__cvta_generic_to_shared(sAl);
    unsigned uBh = (unsigned)__cvta_generic_to_shared(sBh);
    unsigned uBl = (unsigned)__cvta_generic_to_shared(sBl);

    int r0i = (tid*2) >> 2, s0 = (tid*2) & 3;
    int r1i = (tid*2+1) >> 2, s1 = (tid*2+1) & 3;

    #define LOADCH(ch) do{                                                        \
        size_t ko = (size_t)(ch)*32;                                              \
        bool ok0 = (bm+r0i) < MROWS, ok1 = (bm+r1i) < MROWS;                      \
        rAh[0] = ok0 ? *(const uint4*)(g_EmbHi + (size_t)(bm+r0i)*EMB + ko + s0*8) : z4; \
        rAl[0] = ok0 ? *(const uint4*)(g_EmbLo + (size_t)(bm+r0i)*EMB + ko + s0*8) : z4; \
        rAh[1] = ok1 ? *(const uint4*)(g_EmbHi + (size_t)(bm+r1i)*EMB + ko + s1*8) : z4; \
        rAl[1] = ok1 ? *(const uint4*)(g_EmbLo + (size_t)(bm+r1i)*EMB + ko + s1*8) : z4; \
        rBh[0] = *(const uint4*)(g_WihHi + (size_t)(bn+r0i)*EMB + ko + s0*8);     \
        rBl[0] = *(const uint4*)(g_WihLo + (size_t)(bn+r0i)*EMB + ko + s0*8);     \
        rBh[1] = *(const uint4*)(g_WihHi + (size_t)(bn+r1i)*EMB + ko + s1*8);     \
        rBl[1] = *(const uint4*)(g_WihLo + (size_t)(bn+r1i)*EMB + ko + s1*8);     \
    }while(0)

    LOADCH(0);

    for (int ch = 0; ch < 16; ch++){
        __syncthreads();
        *(uint4*)(sAh + r0i*SROW + s0*8) = rAh[0];
        *(uint4*)(sAl + r0i*SROW + s0*8) = rAl[0];
        *(uint4*)(sBh + r0i*SROW + s0*8) = rBh[0];
        *(uint4*)(sBl + r0i*SROW + s0*8) = rBl[0];
        *(uint4*)(sAh + r1i*SROW + s1*8) = rAh[1];
        *(uint4*)(sAl + r1i*SROW + s1*8) = rAl[1];
        *(uint4*)(sBh + r1i*SROW + s1*8) = rBh[1];
        *(uint4*)(sBl + r1i*SROW + s1*8) = rBl[1];
        __syncthreads();
        if (ch+1 < 16) LOADCH(ch+1);

        #pragma unroll
        for (int ks = 0; ks < 2; ks++){
            unsigned ah[2][4], al[2][4], bh[8][2], bl[8][2];
            int arow = wm*32 + (lane & 15);
            int acol = ks*16 + ((lane & 16) ? 8 : 0);
            #pragma unroll
            for (int mt = 0; mt < 2; mt++){
                unsigned off = (unsigned)((arow + mt*16)*SROW + acol) * 2u;
                ldsm4(ah[mt][0], ah[mt][1], ah[mt][2], ah[mt][3], uAh + off);
                ldsm4(al[mt][0], al[mt][1], al[mt][2], al[mt][3], uAl + off);
            }
            int brow = wn*64 + (lane & 7) + ((lane & 16) ? 8 : 0);
            int bcol = ks*16 + ((lane & 8) ? 8 : 0);
            #pragma unroll
            for (int p = 0; p < 4; p++){
                unsigned off = (unsigned)((brow + p*16)*SROW + bcol) * 2u;
                ldsm4(bh[2*p][0], bh[2*p][1], bh[2*p+1][0], bh[2*p+1][1], uBh + off);
                ldsm4(bl[2*p][0], bl[2*p][1], bl[2*p+1][0], bl[2*p+1][1], uBl + off);
            }
            #pragma unroll
            for (int mt = 0; mt < 2; mt++)
                #pragma unroll
                for (int nt = 0; nt < 8; nt++){
                    mma_bf16(acc[mt][nt], ah[mt], bh[nt]);
                    mma_bf16(acc[mt][nt], ah[mt], bl[nt]);
                    mma_bf16(acc[mt][nt], al[mt], bh[nt]);
                }
        }
    }

    #pragma unroll
    for (int mt = 0; mt < 2; mt++){
        int m0 = bm + wm*32 + mt*16 + (lane >> 2);
        int m1 = m0 + 8;
        #pragma unroll
        for (int nt = 0; nt < 8; nt++){
            int n = bn + wn*64 + nt*8 + (lane & 3)*2;
            float b0 = bih[n] + bhh[n], b1 = bih[n+1] + bhh[n+1];
            if (m0 < MROWS)
                *(float2*)(g_XP + (size_t)m0*GATES + n) =
                    make_float2(acc[mt][nt][0] + b0, acc[mt][nt][1] + b1);
            if (m1 < MROWS)
                *(float2*)(g_XP + (size_t)m1*GATES + n) =
                    make_float2(acc[mt][nt][2] + b0, acc[mt][nt][3] + b1);
        }
    }
    #undef LOADCH
}

// ---------------- gates body: g_gpart[slice] = h @ W_hh^T (K-slice 128) -------
__device__ __forceinline__ void gates_body(const float* __restrict__ B, int bn, int Koff,
                                           int tid, float (*sA)[36], float (*sB)[68]){
    const int N = GATES, K = HID;
    int tm = (tid>>4)<<2, tn = (tid&15)<<2;
    int lm = tid>>2, lk = (tid&3)<<2;
    float acc[4][4];
    #pragma unroll
    for(int i=0;i<4;i++){ acc[i][0]=0.f; acc[i][1]=0.f; acc[i][2]=0.f; acc[i][3]=0.f; }
    for (int k0=0;k0<128;k0+=16){
        float4 av = *(const float4*)(g_h + (size_t)lm*K + Koff + k0 + lk);
        sA[lk+0][lm]=av.x; sA[lk+1][lm]=av.y; sA[lk+2][lm]=av.z; sA[lk+3][lm]=av.w;
        #pragma unroll
        for (int r=0;r<2;r++){
            int n = lm + 32*r;
            float4 bv = *(const float4*)(B + (size_t)(bn+n)*K + Koff + k0 + lk);
            sB[lk+0][n]=bv.x; sB[lk+1][n]=bv.y; sB[lk+2][n]=bv.z; sB[lk+3][n]=bv.w;
        }
        __syncthreads();
        #pragma unroll
        for(int kk=0;kk<16;kk++){
            float4 a = *(const float4*)&sA[kk][tm];
            float4 b = *(const float4*)&sB[kk][tn];
            float aa[4]={a.x,a.y,a.z,a.w}, bb[4]={b.x,b.y,b.z,b.w};
            #pragma unroll
            for(int i=0;i<4;i++)
                #pragma unroll
                for(int j=0;j<4;j++) acc[i][j] += aa[i]*bb[j];
        }
        __syncthreads();
    }
    float* dst = g_gpart[Koff >> 7];
    #pragma unroll
    for(int i=0;i<4;i++)
        #pragma unroll
        for(int j=0;j<4;j++)
            dst[(size_t)(tm+i)*N + bn+tn+j] = acc[i][j];
}

__global__ void k_gates(const float* __restrict__ B){
    __shared__ float sA[16][36];
    __shared__ float sB[16][68];
    gates_body(B, blockIdx.x*64, blockIdx.y*128, threadIdx.x, sA, sB);
}

// ---------------- dec body: g_dpart[Ks][t] = hcat @ W_w^T (K-slice 128) -------
__device__ __forceinline__ void dec_body(const float* __restrict__ B, int bn, int Koff,
                                         int tid, int t, float (*sA)[36], float (*sB)[68]){
    const int N = HID, K = HC;
    int tm = (tid>>4)<<2, tn = (tid&15)<<2;
    int lm = tid>>2, lk = (tid&3)<<2;
    float acc[4][4];
    #pragma unroll
    for(int i=0;i<4;i++){ acc[i][0]=0.f; acc[i][1]=0.f; acc[i][2]=0.f; acc[i][3]=0.f; }
    for (int k0=0;k0<128;k0+=16){
        float4 av = *(const float4*)(g_hcat + (size_t)lm*K + Koff + k0 + lk);
        sA[lk+0][lm]=av.x; sA[lk+1][lm]=av.y; sA[lk+2][lm]=av.z; sA[lk+3][lm]=av.w;
        #pragma unroll
        for (int r=0;r<2;r++){
            int n = lm + 32*r;
            float4 bv = *(const float4*)(B + (size_t)(bn+n)*K + Koff + k0 + lk);
            sB[lk+0][n]=bv.x; sB[lk+1][n]=bv.y; sB[lk+2][n]=bv.z; sB[lk+3][n]=bv.w;
        }
        __syncthreads();
        #pragma unroll
        for(int kk=0;kk<16;kk++){
            float4 a = *(const float4*)&sA[kk][tm];
            float4 b = *(const float4*)&sB[kk][tn];
            float aa[4]={a.x,a.y,a.z,a.w}, bb[4]={b.x,b.y,b.z,b.w};
            #pragma unroll
            for(int i=0;i<4;i++)
                #pragma unroll
                for(int j=0;j<4;j++) acc[i][j] += aa[i]*bb[j];
        }
        __syncthreads();
    }
    float* dst = g_dpart[Koff >> 7] + (size_t)t*BATCH*HID;
    #pragma unroll
    for(int i=0;i<4;i++)
        #pragma unroll
        for(int j=0;j<4;j++)
            dst[(size_t)(tm+i)*N + bn+tn+j] = acc[i][j];
}

// ---------------- merged dec(t) + gates(t+1): 768 CTAs ------------------------
__global__ void k_decgates(const float* __restrict__ Ww, const float* __restrict__ Whh,
                           int t){
    __shared__ float sA[16][36];
    __shared__ float sB[16][68];
    int blk = blockIdx.x;
    if (blk < 256){   // dec: 16 N-tiles x 16 K-slices
        dec_body(Ww, (blk & 15)*64, (blk >> 4)*128, threadIdx.x, t, sA, sB);
    } else {          // gates: 64 N-tiles x 8 K-slices
        int g = blk - 256;
        gates_body(Whh, (g & 63)*64, (g >> 6)*128, threadIdx.x, sA, sB);
    }
}

// ---------------- fused LSTM cell + scores + softmax + context -----------------
__global__ void __launch_bounds__(1024,1)
k_cellattn(const float* __restrict__ enc, int t){
    __shared__ float sh[HID];
    __shared__ float ss[SEQ];
    int b = blockIdx.x, j = threadIdx.x;       // j = 0..1023
    size_t gbase = (size_t)b*GATES;
    const float* xp = g_XP + ((size_t)t*BATCH + b)*GATES;
    float gi = xp[j], gf = xp[1024+j], gg = xp[2048+j], go = xp[3072+j];
    #pragma unroll
    for(int s=0;s<8;s++){
        const float* gp = g_gpart[s] + gbase;
        gi += gp[j]; gf += gp[1024+j]; gg += gp[2048+j]; go += gp[3072+j];
    }
    float i_ = 1.f/(1.f+expf(-gi));
    float f_ = 1.f/(1.f+expf(-gf));
    float g_ = tanhf(gg);
    float o_ = 1.f/(1.f+expf(-go));
    int idx  = b*HID + j;
    float c  = f_*g_c[idx] + i_*g_;
    g_c[idx] = c;
    float h  = o_*tanhf(c);
    g_h[idx] = h;
    g_hcat[(size_t)b*HC + j] = h;
    sh[j] = h;
    __syncthreads();
    // scores: 32 warps, warp w handles s = w, w+32
    int warp = j>>5, lane = j&31;
    for (int s=warp; s<SEQ; s+=32){
        const float* e = enc + ((size_t)b*SEQ + s)*HID;
        float acc = 0.f;
        #pragma unroll 8
        for (int k=lane;k<HID;k+=32) acc += sh[k]*e[k];
        #pragma unroll
        for(int o=16;o;o>>=1) acc += __shfl_xor_sync(0xffffffffu, acc, o);
        if (!lane) ss[s] = acc;
    }
    __syncthreads();
    if (j == 0){
        float mx = -1e30f;
        for(int s=0;s<SEQ;s++) mx = fmaxf(mx, ss[s]);
        float sum = 0.f;
        for(int s=0;s<SEQ;s++){ float e = expf(ss[s]-mx); ss[s]=e; sum+=e; }
        float inv = 1.f/sum;
        for(int s=0;s<SEQ;s++) ss[s] *= inv;
    }
    __syncthreads();
    // context: thread j handles hid column j
    const float* e = enc + (size_t)b*SEQ*HID + j;
    float ctx = 0.f;
    #pragma unroll 8
    for (int s=0;s<SEQ;s++) ctx += ss[s]*e[(size_t)s*HID];
    g_hcat[(size_t)b*HC + HID + j] = ctx;
}

// ---------------- tanh reduce (16 slices) -> Dec bf16 hi/lo --------------------
__global__ void k_tanh(const float* __restrict__ bw){
    int idx = blockIdx.x*blockDim.x + threadIdx.x;   // 2016*1024
    float s = bw[idx & 1023];
    #pragma unroll
    for(int p=0;p<16;p++) s += g_dpart[p][idx];
    float th = tanhf(s);
    __nv_bfloat16 hi = __float2bfloat16(th);
    __nv_bfloat16 lo = __float2bfloat16(th - __bfloat162float(hi));
    g_DecHi[idx] = hi;
    g_DecLo[idx] = lo;
}

// ---------------- tensor-core output GEMM --------------------------------------
__global__ void __launch_bounds__(256,1)
k_out_mma(const float* __restrict__ bout, float* __restrict__ out){
    __shared__ __align__(16) __nv_bfloat16 sAh[128*SROW];
    __shared__ __align__(16) __nv_bfloat16 sAl[128*SROW];
    __shared__ __align__(16) __nv_bfloat16 sBh[128*SROW];
    __shared__ __align__(16) __nv_bfloat16 sBl[128*SROW];

    const int bm = blockIdx.y*128, bn = blockIdx.x*128;
    const int tid = threadIdx.x, lane = tid & 31, warp = tid >> 5;
    const int wm = warp & 3, wn = warp >> 2;

    float acc[2][8][4];
    #pragma unroll
    for(int i=0;i<2;i++)
        #pragma unroll
        for(int j=0;j<8;j++){ acc[i][j][0]=0.f; acc[i][j][1]=0.f; acc[i][j][2]=0.f; acc[i][j][3]=0.f; }

    uint4 rAh[2], rAl[2], rBh[2], rBl[2];
    const uint4 z4 = make_uint4(0u,0u,0u,0u);

    unsigned uAh = (unsigned)__cvta_generic_to_shared(sAh);
    unsigned uAl = (unsigned)__cvta_generic_to_shared(sAl);
    unsigned uBh = (unsigned)__cvta_generic_to_shared(sBh);
    unsigned uBl = (unsigned)__cvta_generic_to_shared(sBl);

    int r0i = (tid*2) >> 2, s0 = (tid*2) & 3;
    int r1i = (tid*2+1) >> 2, s1 = (tid*2+1) & 3;

    #define LOADCH(ch) do{                                                        \
        size_t ko = (size_t)(ch)*32;                                              \
        bool ok0 = (bm+r0i) < MROWS, ok1 = (bm+r1i) < MROWS;                      \
        rAh[0] = ok0 ? *(const uint4*)(g_DecHi + (size_t)(bm+r0i)*HID + ko + s0*8) : z4; \
        rAl[0] = ok0 ? *(const uint4*)(g_DecLo + (size_t)(bm+r0i)*HID + ko + s0*8) : z4; \
        rAh[1] = ok1 ? *(const uint4*)(g_DecHi + (size_t)(bm+r1i)*HID + ko + s1*8) : z4; \
        rAl[1] = ok1 ? *(const uint4*)(g_DecLo + (size_t)(bm+r1i)*HID + ko + s1*8) : z4; \
        rBh[0] = *(const uint4*)(g_WoutHi + (size_t)(bn+r0i)*HID + ko + s0*8);    \
        rBl[0] = *(const uint4*)(g_WoutLo + (size_t)(bn+r0i)*HID + ko + s0*8);    \
        rBh[1] = *(const uint4*)(g_WoutHi + (size_t)(bn+r1i)*HID + ko + s1*8);    \
        rBl[1] = *(const uint4*)(g_WoutLo + (size_t)(bn+r1i)*HID + ko + s1*8);    \
    }while(0)

    LOADCH(0);

    for (int ch = 0; ch < 32; ch++){
        __syncthreads();
        *(uint4*)(sAh + r0i*SROW + s0*8) = rAh[0];
        *(uint4*)(sAl + r0i*SROW + s0*8) = rAl[0];
        *(uint4*)(sBh + r0i*SROW + s0*8) = rBh[0];
        *(uint4*)(sBl + r0i*SROW + s0*8) = rBl[0];
        *(uint4*)(sAh + r1i*SROW + s1*8) = rAh[1];
        *(uint4*)(sAl + r1i*SROW + s1*8) = rAl[1];
        *(uint4*)(sBh + r1i*SROW + s1*8) = rBh[1];
        *(uint4*)(sBl + r1i*SROW + s1*8) = rBl[1];
        __syncthreads();
        if (ch+1 < 32) LOADCH(ch+1);

        #pragma unroll
        for (int ks = 0; ks < 2; ks++){
            unsigned ah[2][4], al[2][4], bh[8][2], bl[8][2];
            int arow = wm*32 + (lane & 15);
            int acol = ks*16 + ((lane & 16) ? 8 : 0);
            #pragma unroll
            for (int mt = 0; mt < 2; mt++){
                unsigned off = (unsigned)((arow + mt*16)*SROW + acol) * 2u;
                ldsm4(ah[mt][0], ah[mt][1], ah[mt][2], ah[mt][3], uAh + off);
                ldsm4(al[mt][0], al[mt][1], al[mt][2], al[mt][3], uAl + off);
            }
            int brow = wn*64 + (lane & 7) + ((lane & 16) ? 8 : 0);
            int bcol = ks*16 + ((lane & 8) ? 8 : 0);
            #pragma unroll
            for (int p = 0; p < 4; p++){
                unsigned off = (unsigned)((brow + p*16)*SROW + bcol) * 2u;
                ldsm4(bh[2*p][0], bh[2*p][1], bh[2*p+1][0], bh[2*p+1][1], uBh + off);
                ldsm4(bl[2*p][0], bl[2*p][1], bl[2*p+1][0], bl[2*p+1][1], uBl + off);
            }
            #pragma unroll
            for (int mt = 0; mt < 2; mt++)
                #pragma unroll
                for (int nt = 0; nt < 8; nt++){
                    mma_bf16(acc[mt][nt], ah[mt], bh[nt]);
                    mma_bf16(acc[mt][nt], ah[mt], bl[nt]);
                    mma_bf16(acc[mt][nt], al[mt], bh[nt]);
                }
        }
    }

    #pragma unroll
    for (int mt = 0; mt < 2; mt++){
        int m0 = bm + wm*32 + mt*16 + (lane >> 2);
        int m1 = m0 + 8;
        #pragma unroll
        for (int nt = 0; nt < 8; nt++){
            int n = bn + wn*64 + nt*8 + (lane & 3)*2;
            float b0 = bout[n], b1 = bout[n+1];
            if (m0 < MROWS){
                int t = m0 >> 5, b = m0 & 31;
                float2 v = make_float2(acc[mt][nt][0] + b0, acc[mt][nt][1] + b1);
                *(float2*)(out + (size_t)b*(TSTEPS*VOC) + (size_t)t*VOC + n) = v;
            }
            if (m1 < MROWS){
                int t = m1 >> 5, b = m1 & 31;
                float2 v = make_float2(acc[mt][nt][2] + b0, acc[mt][nt][3] + b1);
                *(float2*)(out + (size_t)b*(TSTEPS*VOC) + (size_t)t*VOC + n) = v;
            }
        }
    }
    #undef LOADCH
}

// ---------------- launch ------------------------------------------------------
extern "C" void kernel_launch(void* const* d_in, const int* in_sizes, int n_in,
                              void* d_out, int out_size){
    const int*   tgt  = (const int*)  d_in[0];
    const float* h0   = (const float*)d_in[1];
    const float* c0   = (const float*)d_in[2];
    const float* enc  = (const float*)d_in[3];
    const float* emb  = (const float*)d_in[4];
    const float* Wih  = (const float*)d_in[5];
    const float* Whh  = (const float*)d_in[6];
    const float* bih  = (const float*)d_in[7];
    const float* bhh  = (const float*)d_in[8];
    const float* Ww   = (const float*)d_in[9];
    const float* bw   = (const float*)d_in[10];
    const float* Wout = (const float*)d_in[11];
    const float* bout = (const float*)d_in[12];
    float* out = (float*)d_out;

    k_init   <<<128, 256>>>(h0, c0);
    k_embed  <<<MROWS, 128>>>(tgt, emb);
    k_cvtWout<<<((size_t)VOC*HID/4)/256, 256>>>(Wout);
    k_cvtWih <<<((size_t)GATES*EMB/4)/256, 256>>>(Wih);
    k_xp_mma <<<dim3(GATES/128, (MROWS+127)/128), 256>>>(bih, bhh);

    k_gates<<<dim3(GATES/64, 8), 128>>>(Whh);   // gates for t=0
    for (int t = 0; t < TSTEPS; t++){
        k_cellattn<<<BATCH, 1024>>>(enc, t);
        k_decgates<<<768, 128>>>(Ww, Whh, t);   // dec(t) + gates(t+1)
    }

    k_tanh<<<(MROWS*HID)/256, 256>>>(bw);
    k_out_mma<<<dim3(VOC/128, (MROWS+127)/128), 256>>>(bout, out);
}

// round 12
// speedup vs baseline: 2.3112x; 1.1201x over previous
#include <cuda_runtime.h>
#include <cuda_bf16.h>
#include <math.h>

// Problem dims
#define TSTEPS 63
#define BATCH  32
#define SEQ    64
#define HID    1024
#define EMB    512
#define VOC    32000
#define GATES  4096
#define HC     2048
#define MROWS  (TSTEPS*BATCH)   // 2016

// ---------------- scratch (static device globals; no runtime alloc) -------------
__device__ float g_XP  [MROWS*GATES];
__device__ float g_c   [BATCH*HID];
__device__ float g_gpart[8][BATCH*GATES];
__device__ float g_dpart[16][MROWS*HID];
__device__ __nv_bfloat16 g_hcHi [BATCH*HC];     // [h | context] bf16 hi
__device__ __nv_bfloat16 g_hcLo [BATCH*HC];     // [h | context] bf16 lo
__device__ __nv_bfloat16 g_EmbHi [MROWS*EMB];
__device__ __nv_bfloat16 g_EmbLo [MROWS*EMB];
__device__ __nv_bfloat16 g_WihHi [(size_t)GATES*EMB];
__device__ __nv_bfloat16 g_WihLo [(size_t)GATES*EMB];
__device__ __nv_bfloat16 g_WhhHi [(size_t)GATES*HID];
__device__ __nv_bfloat16 g_WhhLo [(size_t)GATES*HID];
__device__ __nv_bfloat16 g_WwHi  [(size_t)HID*HC];
__device__ __nv_bfloat16 g_WwLo  [(size_t)HID*HC];
__device__ __nv_bfloat16 g_DecHi [MROWS*HID];
__device__ __nv_bfloat16 g_DecLo [MROWS*HID];
__device__ __nv_bfloat16 g_WoutHi[(size_t)VOC*HID];
__device__ __nv_bfloat16 g_WoutLo[(size_t)VOC*HID];

// ---------------- init: c0 fp32; h0 -> hcat hi/lo -----------------------------
__global__ void k_init(const float* __restrict__ h0, const float* __restrict__ c0){
    int i = blockIdx.x*blockDim.x + threadIdx.x;
    if (i < BATCH*HID){
        g_c[i] = c0[i];
        int b = i >> 10, j = i & 1023;
        float v = h0[i];
        __nv_bfloat16 hi = __float2bfloat16(v);
        __nv_bfloat16 lo = __float2bfloat16(v - __bfloat162float(hi));
        g_hcHi[(size_t)b*HC + j] = hi;
        g_hcLo[(size_t)b*HC + j] = lo;
    }
}

// ---------------- embedding gather -> bf16 hi/lo ------------------------------
__global__ void k_embed(const int* __restrict__ tgt, const float* __restrict__ emb){
    int r = blockIdx.x;              // 0..2015
    int t = r >> 5, b = r & 31;
    int tok = tgt[b*64 + t];
    float4 v = ((const float4*)(emb + (size_t)tok*EMB))[threadIdx.x];  // 128 thr
    __nv_bfloat16 h0 = __float2bfloat16(v.x);
    __nv_bfloat16 h1 = __float2bfloat16(v.y);
    __nv_bfloat16 h2 = __float2bfloat16(v.z);
    __nv_bfloat16 h3 = __float2bfloat16(v.w);
    __nv_bfloat16 l0 = __float2bfloat16(v.x - __bfloat162float(h0));
    __nv_bfloat16 l1 = __float2bfloat16(v.y - __bfloat162float(h1));
    __nv_bfloat16 l2 = __float2bfloat16(v.z - __bfloat162float(h2));
    __nv_bfloat16 l3 = __float2bfloat16(v.w - __bfloat162float(h3));
    size_t o = (size_t)r*EMB + threadIdx.x*4;
    *(__nv_bfloat162*)(g_EmbHi + o)     = __nv_bfloat162(h0,h1);
    *(__nv_bfloat162*)(g_EmbHi + o + 2) = __nv_bfloat162(h2,h3);
    *(__nv_bfloat162*)(g_EmbLo + o)     = __nv_bfloat162(l0,l1);
    *(__nv_bfloat162*)(g_EmbLo + o + 2) = __nv_bfloat162(l2,l3);
}

// ---------------- fp32 -> bf16 hi/lo converters (dest named in device code) ----
#define CVT_BODY(HI, LO)                                                          \
    size_t i = (size_t)blockIdx.x*blockDim.x + threadIdx.x;                       \
    float4 v = ((const float4*)W)[i];                                             \
    __nv_bfloat16 h0 = __float2bfloat16(v.x);                                     \
    __nv_bfloat16 h1 = __float2bfloat16(v.y);                                     \
    __nv_bfloat16 h2 = __float2bfloat16(v.z);                                     \
    __nv_bfloat16 h3 = __float2bfloat16(v.w);                                     \
    __nv_bfloat16 l0 = __float2bfloat16(v.x - __bfloat162float(h0));              \
    __nv_bfloat16 l1 = __float2bfloat16(v.y - __bfloat162float(h1));              \
    __nv_bfloat16 l2 = __float2bfloat16(v.z - __bfloat162float(h2));              \
    __nv_bfloat16 l3 = __float2bfloat16(v.w - __bfloat162float(h3));              \
    __nv_bfloat162* Hi = (__nv_bfloat162*)(HI);                                   \
    __nv_bfloat162* Lo = (__nv_bfloat162*)(LO);                                   \
    Hi[2*i+0] = __nv_bfloat162(h0,h1);                                            \
    Hi[2*i+1] = __nv_bfloat162(h2,h3);                                            \
    Lo[2*i+0] = __nv_bfloat162(l0,l1);                                            \
    Lo[2*i+1] = __nv_bfloat162(l2,l3);

__global__ void k_cvtWout(const float* __restrict__ W){ CVT_BODY(g_WoutHi, g_WoutLo) }
__global__ void k_cvtWih (const float* __restrict__ W){ CVT_BODY(g_WihHi,  g_WihLo ) }
__global__ void k_cvtWhh (const float* __restrict__ W){ CVT_BODY(g_WhhHi,  g_WhhLo ) }
__global__ void k_cvtWw  (const float* __restrict__ W){ CVT_BODY(g_WwHi,   g_WwLo  ) }

// ---------------- tensor-core primitives --------------------------------------
__device__ __forceinline__ void ldsm4(unsigned &r0, unsigned &r1, unsigned &r2, unsigned &r3,
                                      unsigned addr){
    asm volatile("ldmatrix.sync.aligned.m8n8.x4.shared.b16 {%0,%1,%2,%3}, [%4];\n"
        : "=r"(r0),"=r"(r1),"=r"(r2),"=r"(r3) : "r"(addr));
}
__device__ __forceinline__ void mma_bf16(float* c, const unsigned* a, const unsigned* b){
    asm volatile("mma.sync.aligned.m16n8k16.row.col.f32.bf16.bf16.f32 "
        "{%0,%1,%2,%3}, {%4,%5,%6,%7}, {%8,%9}, {%0,%1,%2,%3};\n"
        : "+f"(c[0]),"+f"(c[1]),"+f"(c[2]),"+f"(c[3])
        : "r"(a[0]),"r"(a[1]),"r"(a[2]),"r"(a[3]), "r"(b[0]),"r"(b[1]));
}

#define SROW 40   // padded smem row stride in bf16 (80 bytes -> conflict-free ldmatrix)

// ---------------- XP GEMM (tensor core): Emb(2016x512) @ Wih^T + biases -------
__global__ void __launch_bounds__(256,1)
k_xp_mma(const float* __restrict__ bih, const float* __restrict__ bhh){
    __shared__ __align__(16) __nv_bfloat16 sAh[128*SROW];
    __shared__ __align__(16) __nv_bfloat16 sAl[128*SROW];
    __shared__ __align__(16) __nv_bfloat16 sBh[128*SROW];
    __shared__ __align__(16) __nv_bfloat16 sBl[128*SROW];

    const int bm = blockIdx.y*128, bn = blockIdx.x*128;
    const int tid = threadIdx.x, lane = tid & 31, warp = tid >> 5;
    const int wm = warp & 3, wn = warp >> 2;

    float acc[2][8][4];
    #pragma unroll
    for(int i=0;i<2;i++)
        #pragma unroll
        for(int j=0;j<8;j++){ acc[i][j][0]=0.f; acc[i][j][1]=0.f; acc[i][j][2]=0.f; acc[i][j][3]=0.f; }

    uint4 rAh[2], rAl[2], rBh[2], rBl[2];
    const uint4 z4 = make_uint4(0u,0u,0u,0u);

    unsigned uAh = (unsigned)__cvta_generic_to_shared(sAh);
    unsigned uAl = (unsigned)__cvta_generic_to_shared(sAl);
    unsigned uBh = (unsigned)__cvta_generic_to_shared(sBh);
    unsigned uBl = (unsigned)__cvta_generic_to_shared(sBl);

    int r0i = (tid*2) >> 2, s0 = (tid*2) & 3;
    int r1i = (tid*2+1) >> 2, s1 = (tid*2+1) & 3;

    #define LOADCH(ch) do{                                                        \
        size_t ko = (size_t)(ch)*32;                                              \
        bool ok0 = (bm+r0i) < MROWS, ok1 = (bm+r1i) < MROWS;                      \
        rAh[0] = ok0 ? *(const uint4*)(g_EmbHi + (size_t)(bm+r0i)*EMB + ko + s0*8) : z4; \
        rAl[0] = ok0 ? *(const uint4*)(g_EmbLo + (size_t)(bm+r0i)*EMB + ko + s0*8) : z4; \
        rAh[1] = ok1 ? *(const uint4*)(g_EmbHi + (size_t)(bm+r1i)*EMB + ko + s1*8) : z4; \
        rAl[1] = ok1 ? *(const uint4*)(g_EmbLo + (size_t)(bm+r1i)*EMB + ko + s1*8) : z4; \
        rBh[0] = *(const uint4*)(g_WihHi + (size_t)(bn+r0i)*EMB + ko + s0*8);     \
        rBl[0] = *(const uint4*)(g_WihLo + (size_t)(bn+r0i)*EMB + ko + s0*8);     \
        rBh[1] = *(const uint4*)(g_WihHi + (size_t)(bn+r1i)*EMB + ko + s1*8);     \
        rBl[1] = *(const uint4*)(g_WihLo + (size_t)(bn+r1i)*EMB + ko + s1*8);     \
    }while(0)

    LOADCH(0);

    for (int ch = 0; ch < 16; ch++){
        __syncthreads();
        *(uint4*)(sAh + r0i*SROW + s0*8) = rAh[0];
        *(uint4*)(sAl + r0i*SROW + s0*8) = rAl[0];
        *(uint4*)(sBh + r0i*SROW + s0*8) = rBh[0];
        *(uint4*)(sBl + r0i*SROW + s0*8) = rBl[0];
        *(uint4*)(sAh + r1i*SROW + s1*8) = rAh[1];
        *(uint4*)(sAl + r1i*SROW + s1*8) = rAl[1];
        *(uint4*)(sBh + r1i*SROW + s1*8) = rBh[1];
        *(uint4*)(sBl + r1i*SROW + s1*8) = rBl[1];
        __syncthreads();
        if (ch+1 < 16) LOADCH(ch+1);

        #pragma unroll
        for (int ks = 0; ks < 2; ks++){
            unsigned ah[2][4], al[2][4], bh[8][2], bl[8][2];
            int arow = wm*32 + (lane & 15);
            int acol = ks*16 + ((lane & 16) ? 8 : 0);
            #pragma unroll
            for (int mt = 0; mt < 2; mt++){
                unsigned off = (unsigned)((arow + mt*16)*SROW + acol) * 2u;
                ldsm4(ah[mt][0], ah[mt][1], ah[mt][2], ah[mt][3], uAh + off);
                ldsm4(al[mt][0], al[mt][1], al[mt][2], al[mt][3], uAl + off);
            }
            int brow = wn*64 + (lane & 7) + ((lane & 16) ? 8 : 0);
            int bcol = ks*16 + ((lane & 8) ? 8 : 0);
            #pragma unroll
            for (int p = 0; p < 4; p++){
                unsigned off = (unsigned)((brow + p*16)*SROW + bcol) * 2u;
                ldsm4(bh[2*p][0], bh[2*p][1], bh[2*p+1][0], bh[2*p+1][1], uBh + off);
                ldsm4(bl[2*p][0], bl[2*p][1], bl[2*p+1][0], bl[2*p+1][1], uBl + off);
            }
            #pragma unroll
            for (int mt = 0; mt < 2; mt++)
                #pragma unroll
                for (int nt = 0; nt < 8; nt++){
                    mma_bf16(acc[mt][nt], ah[mt], bh[nt]);
                    mma_bf16(acc[mt][nt], ah[mt], bl[nt]);
                    mma_bf16(acc[mt][nt], al[mt], bh[nt]);
                }
        }
    }

    #pragma unroll
    for (int mt = 0; mt < 2; mt++){
        int m0 = bm + wm*32 + mt*16 + (lane >> 2);
        int m1 = m0 + 8;
        #pragma unroll
        for (int nt = 0; nt < 8; nt++){
            int n = bn + wn*64 + nt*8 + (lane & 3)*2;
            float b0 = bih[n] + bhh[n], b1 = bih[n+1] + bhh[n+1];
            if (m0 < MROWS)
                *(float2*)(g_XP + (size_t)m0*GATES + n) =
                    make_float2(acc[mt][nt][0] + b0, acc[mt][nt][1] + b1);
            if (m1 < MROWS)
                *(float2*)(g_XP + (size_t)m1*GATES + n) =
                    make_float2(acc[mt][nt][2] + b0, acc[mt][nt][3] + b1);
        }
    }
    #undef LOADCH
}

// ---------------- tensor-core dec(t) + gates(t+1) -----------------------------
// gates (blk 0..127):  g_gpart[Ks]  = h    @ Whh^T  (M=32, N-tile 256, K-slice 128)
// dec   (blk 128..191): g_dpart[Ks][t] = hcat @ Ww^T (M=32, N-tile 256, K-slice 128)
// A = g_hcHi/Lo rows (stride HC); gates use K<1024 (h half), dec the full 2048.
__global__ void __launch_bounds__(128,1)
k_dg_mma(int t){
    __shared__ __align__(16) __nv_bfloat16 sAh[32*SROW];
    __shared__ __align__(16) __nv_bfloat16 sAl[32*SROW];
    __shared__ __align__(16) __nv_bfloat16 sBh[256*SROW];
    __shared__ __align__(16) __nv_bfloat16 sBl[256*SROW];

    int blk = blockIdx.x;
    int tid = threadIdx.x, lane = tid & 31, wn = tid >> 5;   // 4 warps
    int bn, Koff, Kdim, Nstr;
    const __nv_bfloat16 *Bh, *Bl;
    float* dst;
    if (blk < 128){   // gates: 16 N-tiles x 8 K-slices
        bn = (blk & 15)*256; Koff = (blk >> 4)*128; Kdim = HID; Nstr = GATES;
        Bh = g_WhhHi; Bl = g_WhhLo; dst = g_gpart[blk >> 4];
    } else {          // dec: 4 N-tiles x 16 K-slices
        int g = blk - 128;
        bn = (g & 3)*256; Koff = (g >> 2)*128; Kdim = HC; Nstr = HID;
        Bh = g_WwHi; Bl = g_WwLo; dst = g_dpart[g >> 2] + (size_t)t*BATCH*HID;
    }

    float acc[2][8][4];
    #pragma unroll
    for(int i=0;i<2;i++)
        #pragma unroll
        for(int j=0;j<8;j++){ acc[i][j][0]=0.f; acc[i][j][1]=0.f; acc[i][j][2]=0.f; acc[i][j][3]=0.f; }

    unsigned uAh = (unsigned)__cvta_generic_to_shared(sAh);
    unsigned uAl = (unsigned)__cvta_generic_to_shared(sAl);
    unsigned uBh = (unsigned)__cvta_generic_to_shared(sBh);
    unsigned uBl = (unsigned)__cvta_generic_to_shared(sBl);

    int tr = tid >> 2, seg = tid & 3;     // tr 0..31, seg 0..3 (32 cols per chunk)

    for (int ch = 0; ch < 4; ch++){
        int ko = Koff + ch*32 + seg*8;
        __syncthreads();
        // A: 32 rows x 32 cols (one uint4 per thread)
        *(uint4*)(sAh + tr*SROW + seg*8) = *(const uint4*)(g_hcHi + (size_t)tr*HC + ko);
        *(uint4*)(sAl + tr*SROW + seg*8) = *(const uint4*)(g_hcLo + (size_t)tr*HC + ko);
        // B: 256 rows x 32 cols (8 uint4 per thread per matrix)
        #pragma unroll
        for (int i = 0; i < 8; i++){
            int row = tr + 32*i;
            *(uint4*)(sBh + row*SROW + seg*8) = *(const uint4*)(Bh + (size_t)(bn+row)*Kdim + ko);
            *(uint4*)(sBl + row*SROW + seg*8) = *(const uint4*)(Bl + (size_t)(bn+row)*Kdim + ko);
        }
        __syncthreads();

        #pragma unroll
        for (int ks = 0; ks < 2; ks++){
            unsigned ah[2][4], al[2][4], bh[8][2], bl[8][2];
            int arow = (lane & 15);                         // wm = 0
            int acol = ks*16 + ((lane & 16) ? 8 : 0);
            #pragma unroll
            for (int mt = 0; mt < 2; mt++){
                unsigned off = (unsigned)((arow + mt*16)*SROW + acol) * 2u;
                ldsm4(ah[mt][0], ah[mt][1], ah[mt][2], ah[mt][3], uAh + off);
                ldsm4(al[mt][0], al[mt][1], al[mt][2], al[mt][3], uAl + off);
            }
            int brow = wn*64 + (lane & 7) + ((lane & 16) ? 8 : 0);
            int bcol = ks*16 + ((lane & 8) ? 8 : 0);
            #pragma unroll
            for (int p = 0; p < 4; p++){
                unsigned off = (unsigned)((brow + p*16)*SROW + bcol) * 2u;
                ldsm4(bh[2*p][0], bh[2*p][1], bh[2*p+1][0], bh[2*p+1][1], uBh + off);
                ldsm4(bl[2*p][0], bl[2*p][1], bl[2*p+1][0], bl[2*p+1][1], uBl + off);
            }
            #pragma unroll
            for (int mt = 0; mt < 2; mt++)
                #pragma unroll
                for (int nt = 0; nt < 8; nt++){
                    mma_bf16(acc[mt][nt], ah[mt], bh[nt]);
                    mma_bf16(acc[mt][nt], ah[mt], bl[nt]);
                    mma_bf16(acc[mt][nt], al[mt], bh[nt]);
                }
        }
    }

    // epilogue: fp32 partials (no bias)
    #pragma unroll
    for (int mt = 0; mt < 2; mt++){
        int m0 = mt*16 + (lane >> 2);
        int m1 = m0 + 8;
        #pragma unroll
        for (int nt = 0; nt < 8; nt++){
            int n = bn + wn*64 + nt*8 + (lane & 3)*2;
            *(float2*)(dst + (size_t)m0*Nstr + n) = make_float2(acc[mt][nt][0], acc[mt][nt][1]);
            *(float2*)(dst + (size_t)m1*Nstr + n) = make_float2(acc[mt][nt][2], acc[mt][nt][3]);
        }
    }
}

// ---------------- fused LSTM cell + scores + softmax + context -----------------
__global__ void __launch_bounds__(1024,1)
k_cellattn(const float* __restrict__ enc, int t){
    __shared__ float sh[HID];
    __shared__ float ss[SEQ];
    int b = blockIdx.x, j = threadIdx.x;       // j = 0..1023
    size_t gbase = (size_t)b*GATES;
    const float* xp = g_XP + ((size_t)t*BATCH + b)*GATES;
    float gi = xp[j], gf = xp[1024+j], gg = xp[2048+j], go = xp[3072+j];
    #pragma unroll
    for(int s=0;s<8;s++){
        const float* gp = g_gpart[s] + gbase;
        gi += gp[j]; gf += gp[1024+j]; gg += gp[2048+j]; go += gp[3072+j];
    }
    float i_ = 1.f/(1.f+expf(-gi));
    float f_ = 1.f/(1.f+expf(-gf));
    float g_ = tanhf(gg);
    float o_ = 1.f/(1.f+expf(-go));
    int idx  = b*HID + j;
    float c  = f_*g_c[idx] + i_*g_;
    g_c[idx] = c;
    float h  = o_*tanhf(c);
    {
        __nv_bfloat16 hi = __float2bfloat16(h);
        __nv_bfloat16 lo = __float2bfloat16(h - __bfloat162float(hi));
        g_hcHi[(size_t)b*HC + j] = hi;
        g_hcLo[(size_t)b*HC + j] = lo;
    }
    sh[j] = h;
    __syncthreads();
    // scores: 32 warps, warp w handles s = w, w+32
    int warp = j>>5, lane = j&31;
    for (int s=warp; s<SEQ; s+=32){
        const float* e = enc + ((size_t)b*SEQ + s)*HID;
        float acc = 0.f;
        #pragma unroll 8
        for (int k=lane;k<HID;k+=32) acc += sh[k]*e[k];
        #pragma unroll
        for(int o=16;o;o>>=1) acc += __shfl_xor_sync(0xffffffffu, acc, o);
        if (!lane) ss[s] = acc;
    }
    __syncthreads();
    if (j == 0){
        float mx = -1e30f;
        for(int s=0;s<SEQ;s++) mx = fmaxf(mx, ss[s]);
        float sum = 0.f;
        for(int s=0;s<SEQ;s++){ float e = expf(ss[s]-mx); ss[s]=e; sum+=e; }
        float inv = 1.f/sum;
        for(int s=0;s<SEQ;s++) ss[s] *= inv;
    }
    __syncthreads();
    // context: thread j handles hid column j
    const float* e = enc + (size_t)b*SEQ*HID + j;
    float ctx = 0.f;
    #pragma unroll 8
    for (int s=0;s<SEQ;s++) ctx += ss[s]*e[(size_t)s*HID];
    {
        __nv_bfloat16 hi = __float2bfloat16(ctx);
        __nv_bfloat16 lo = __float2bfloat16(ctx - __bfloat162float(hi));
        g_hcHi[(size_t)b*HC + HID + j] = hi;
        g_hcLo[(size_t)b*HC + HID + j] = lo;
    }
}

// ---------------- tanh reduce (16 slices) -> Dec bf16 hi/lo --------------------
__global__ void k_tanh(const float* __restrict__ bw){
    int idx = blockIdx.x*blockDim.x + threadIdx.x;   // 2016*1024
    float s = bw[idx & 1023];
    #pragma unroll
    for(int p=0;p<16;p++) s += g_dpart[p][idx];
    float th = tanhf(s);
    __nv_bfloat16 hi = __float2bfloat16(th);
    __nv_bfloat16 lo = __float2bfloat16(th - __bfloat162float(hi));
    g_DecHi[idx] = hi;
    g_DecLo[idx] = lo;
}

// ---------------- tensor-core output GEMM --------------------------------------
__global__ void __launch_bounds__(256,1)
k_out_mma(const float* __restrict__ bout, float* __restrict__ out){
    __shared__ __align__(16) __nv_bfloat16 sAh[128*SROW];
    __shared__ __align__(16) __nv_bfloat16 sAl[128*SROW];
    __shared__ __align__(16) __nv_bfloat16 sBh[128*SROW];
    __shared__ __align__(16) __nv_bfloat16 sBl[128*SROW];

    const int bm = blockIdx.y*128, bn = blockIdx.x*128;
    const int tid = threadIdx.x, lane = tid & 31, warp = tid >> 5;
    const int wm = warp & 3, wn = warp >> 2;

    float acc[2][8][4];
    #pragma unroll
    for(int i=0;i<2;i++)
        #pragma unroll
        for(int j=0;j<8;j++){ acc[i][j][0]=0.f; acc[i][j][1]=0.f; acc[i][j][2]=0.f; acc[i][j][3]=0.f; }

    uint4 rAh[2], rAl[2], rBh[2], rBl[2];
    const uint4 z4 = make_uint4(0u,0u,0u,0u);

    unsigned uAh = (unsigned)__cvta_generic_to_shared(sAh);
    unsigned uAl = (unsigned)__cvta_generic_to_shared(sAl);
    unsigned uBh = (unsigned)__cvta_generic_to_shared(sBh);
    unsigned uBl = (unsigned)__cvta_generic_to_shared(sBl);

    int r0i = (tid*2) >> 2, s0 = (tid*2) & 3;
    int r1i = (tid*2+1) >> 2, s1 = (tid*2+1) & 3;

    #define LOADCH(ch) do{                                                        \
        size_t ko = (size_t)(ch)*32;                                              \
        bool ok0 = (bm+r0i) < MROWS, ok1 = (bm+r1i) < MROWS;                      \
        rAh[0] = ok0 ? *(const uint4*)(g_DecHi + (size_t)(bm+r0i)*HID + ko + s0*8) : z4; \
        rAl[0] = ok0 ? *(const uint4*)(g_DecLo + (size_t)(bm+r0i)*HID + ko + s0*8) : z4; \
        rAh[1] = ok1 ? *(const uint4*)(g_DecHi + (size_t)(bm+r1i)*HID + ko + s1*8) : z4; \
        rAl[1] = ok1 ? *(const uint4*)(g_DecLo + (size_t)(bm+r1i)*HID + ko + s1*8) : z4; \
        rBh[0] = *(const uint4*)(g_WoutHi + (size_t)(bn+r0i)*HID + ko + s0*8);    \
        rBl[0] = *(const uint4*)(g_WoutLo + (size_t)(bn+r0i)*HID + ko + s0*8);    \
        rBh[1] = *(const uint4*)(g_WoutHi + (size_t)(bn+r1i)*HID + ko + s1*8);    \
        rBl[1] = *(const uint4*)(g_WoutLo + (size_t)(bn+r1i)*HID + ko + s1*8);    \
    }while(0)

    LOADCH(0);

    for (int ch = 0; ch < 32; ch++){
        __syncthreads();
        *(uint4*)(sAh + r0i*SROW + s0*8) = rAh[0];
        *(uint4*)(sAl + r0i*SROW + s0*8) = rAl[0];
        *(uint4*)(sBh + r0i*SROW + s0*8) = rBh[0];
        *(uint4*)(sBl + r0i*SROW + s0*8) = rBl[0];
        *(uint4*)(sAh + r1i*SROW + s1*8) = rAh[1];
        *(uint4*)(sAl + r1i*SROW + s1*8) = rAl[1];
        *(uint4*)(sBh + r1i*SROW + s1*8) = rBh[1];
        *(uint4*)(sBl + r1i*SROW + s1*8) = rBl[1];
        __syncthreads();
        if (ch+1 < 32) LOADCH(ch+1);

        #pragma unroll
        for (int ks = 0; ks < 2; ks++){
            unsigned ah[2][4], al[2][4], bh[8][2], bl[8][2];
            int arow = wm*32 + (lane & 15);
            int acol = ks*16 + ((lane & 16) ? 8 : 0);
            #pragma unroll
            for (int mt = 0; mt < 2; mt++){
                unsigned off = (unsigned)((arow + mt*16)*SROW + acol) * 2u;
                ldsm4(ah[mt][0], ah[mt][1], ah[mt][2], ah[mt][3], uAh + off);
                ldsm4(al[mt][0], al[mt][1], al[mt][2], al[mt][3], uAl + off);
            }
            int brow = wn*64 + (lane & 7) + ((lane & 16) ? 8 : 0);
            int bcol = ks*16 + ((lane & 8) ? 8 : 0);
            #pragma unroll
            for (int p = 0; p < 4; p++){
                unsigned off = (unsigned)((brow + p*16)*SROW + bcol) * 2u;
                ldsm4(bh[2*p][0], bh[2*p][1], bh[2*p+1][0], bh[2*p+1][1], uBh + off);
                ldsm4(bl[2*p][0], bl[2*p][1], bl[2*p+1][0], bl[2*p+1][1], uBl + off);
            }
            #pragma unroll
            for (int mt = 0; mt < 2; mt++)
                #pragma unroll
                for (int nt = 0; nt < 8; nt++){
                    mma_bf16(acc[mt][nt], ah[mt], bh[nt]);
                    mma_bf16(acc[mt][nt], ah[mt], bl[nt]);
                    mma_bf16(acc[mt][nt], al[mt], bh[nt]);
                }
        }
    }

    #pragma unroll
    for (int mt = 0; mt < 2; mt++){
        int m0 = bm + wm*32 + mt*16 + (lane >> 2);
        int m1 = m0 + 8;
        #pragma unroll
        for (int nt = 0; nt < 8; nt++){
            int n = bn + wn*64 + nt*8 + (lane & 3)*2;
            float b0 = bout[n], b1 = bout[n+1];
            if (m0 < MROWS){
                int t = m0 >> 5, b = m0 & 31;
                float2 v = make_float2(acc[mt][nt][0] + b0, acc[mt][nt][1] + b1);
                *(float2*)(out + (size_t)b*(TSTEPS*VOC) + (size_t)t*VOC + n) = v;
            }
            if (m1 < MROWS){
                int t = m1 >> 5, b = m1 & 31;
                float2 v = make_float2(acc[mt][nt][2] + b0, acc[mt][nt][3] + b1);
                *(float2*)(out + (size_t)b*(TSTEPS*VOC) + (size_t)t*VOC + n) = v;
            }
        }
    }
    #undef LOADCH
}

// ---------------- launch ------------------------------------------------------
extern "C" void kernel_launch(void* const* d_in, const int* in_sizes, int n_in,
                              void* d_out, int out_size){
    const int*   tgt  = (const int*)  d_in[0];
    const float* h0   = (const float*)d_in[1];
    const float* c0   = (const float*)d_in[2];
    const float* enc  = (const float*)d_in[3];
    const float* emb  = (const float*)d_in[4];
    const float* Wih  = (const float*)d_in[5];
    const float* Whh  = (const float*)d_in[6];
    const float* bih  = (const float*)d_in[7];
    const float* bhh  = (const float*)d_in[8];
    const float* Ww   = (const float*)d_in[9];
    const float* bw   = (const float*)d_in[10];
    const float* Wout = (const float*)d_in[11];
    const float* bout = (const float*)d_in[12];
    float* out = (float*)d_out;

    k_init   <<<128, 256>>>(h0, c0);
    k_embed  <<<MROWS, 128>>>(tgt, emb);
    k_cvtWout<<<((size_t)VOC*HID/4)/256, 256>>>(Wout);
    k_cvtWih <<<((size_t)GATES*EMB/4)/256, 256>>>(Wih);
    k_cvtWhh <<<((size_t)GATES*HID/4)/256, 256>>>(Whh);
    k_cvtWw  <<<((size_t)HID*HC/4)/256, 256>>>(Ww);
    k_xp_mma <<<dim3(GATES/128, (MROWS+127)/128), 256>>>(bih, bhh);

    k_dg_mma<<<128, 128>>>(0);                  // prolog: gates(0) only
    for (int t = 0; t < TSTEPS; t++){
        k_cellattn<<<BATCH, 1024>>>(enc, t);
        k_dg_mma  <<<192, 128>>>(t);            // dec(t) + gates(t+1)
    }

    k_tanh<<<(MROWS*HID)/256, 256>>>(bw);
    k_out_mma<<<dim3(VOC/128, (MROWS+127)/128), 256>>>(bout, out);
}

// round 13
// speedup vs baseline: 2.3778x; 1.0288x over previous
#include <cuda_runtime.h>
#include <cuda_bf16.h>
#include <math.h>

// Problem dims
#define TSTEPS 63
#define BATCH  32
#define SEQ    64
#define HID    1024
#define EMB    512
#define VOC    32000
#define GATES  4096
#define HC     2048
#define MROWS  (TSTEPS*BATCH)   // 2016

// ---------------- scratch (static device globals; no runtime alloc) -------------
__device__ float g_XP  [MROWS*GATES];
__device__ float g_c   [BATCH*HID];
__device__ float g_gpart[8][BATCH*GATES];
__device__ float g_dpart[16][MROWS*HID];
__device__ __nv_bfloat16 g_hcHi [BATCH*HC];     // [h | context] bf16 hi
__device__ __nv_bfloat16 g_hcLo [BATCH*HC];     // [h | context] bf16 lo
__device__ __nv_bfloat16 g_EmbHi [MROWS*EMB];
__device__ __nv_bfloat16 g_EmbLo [MROWS*EMB];
__device__ __nv_bfloat16 g_WihHi [(size_t)GATES*EMB];
__device__ __nv_bfloat16 g_WihLo [(size_t)GATES*EMB];
__device__ __nv_bfloat16 g_WhhHi [(size_t)GATES*HID];
__device__ __nv_bfloat16 g_WhhLo [(size_t)GATES*HID];
__device__ __nv_bfloat16 g_WwHi  [(size_t)HID*HC];
__device__ __nv_bfloat16 g_WwLo  [(size_t)HID*HC];
__device__ __nv_bfloat16 g_DecHi [MROWS*HID];
__device__ __nv_bfloat16 g_DecLo [MROWS*HID];
__device__ __nv_bfloat16 g_WoutHi[(size_t)VOC*HID];
__device__ __nv_bfloat16 g_WoutLo[(size_t)VOC*HID];

// ---------------- init: c0 fp32; h0 -> hcat hi/lo -----------------------------
__global__ void k_init(const float* __restrict__ h0, const float* __restrict__ c0){
    int i = blockIdx.x*blockDim.x + threadIdx.x;
    if (i < BATCH*HID){
        g_c[i] = c0[i];
        int b = i >> 10, j = i & 1023;
        float v = h0[i];
        __nv_bfloat16 hi = __float2bfloat16(v);
        __nv_bfloat16 lo = __float2bfloat16(v - __bfloat162float(hi));
        g_hcHi[(size_t)b*HC + j] = hi;
        g_hcLo[(size_t)b*HC + j] = lo;
    }
}

// ---------------- embedding gather -> bf16 hi/lo ------------------------------
__global__ void k_embed(const int* __restrict__ tgt, const float* __restrict__ emb){
    int r = blockIdx.x;              // 0..2015
    int t = r >> 5, b = r & 31;
    int tok = tgt[b*64 + t];
    float4 v = ((const float4*)(emb + (size_t)tok*EMB))[threadIdx.x];  // 128 thr
    __nv_bfloat16 h0 = __float2bfloat16(v.x);
    __nv_bfloat16 h1 = __float2bfloat16(v.y);
    __nv_bfloat16 h2 = __float2bfloat16(v.z);
    __nv_bfloat16 h3 = __float2bfloat16(v.w);
    __nv_bfloat16 l0 = __float2bfloat16(v.x - __bfloat162float(h0));
    __nv_bfloat16 l1 = __float2bfloat16(v.y - __bfloat162float(h1));
    __nv_bfloat16 l2 = __float2bfloat16(v.z - __bfloat162float(h2));
    __nv_bfloat16 l3 = __float2bfloat16(v.w - __bfloat162float(h3));
    size_t o = (size_t)r*EMB + threadIdx.x*4;
    *(__nv_bfloat162*)(g_EmbHi + o)     = __nv_bfloat162(h0,h1);
    *(__nv_bfloat162*)(g_EmbHi + o + 2) = __nv_bfloat162(h2,h3);
    *(__nv_bfloat162*)(g_EmbLo + o)     = __nv_bfloat162(l0,l1);
    *(__nv_bfloat162*)(g_EmbLo + o + 2) = __nv_bfloat162(l2,l3);
}

// ---------------- fp32 -> bf16 hi/lo converters (dest named in device code) ----
#define CVT_BODY(HI, LO)                                                          \
    size_t i = (size_t)blockIdx.x*blockDim.x + threadIdx.x;                       \
    float4 v = ((const float4*)W)[i];                                             \
    __nv_bfloat16 h0 = __float2bfloat16(v.x);                                     \
    __nv_bfloat16 h1 = __float2bfloat16(v.y);                                     \
    __nv_bfloat16 h2 = __float2bfloat16(v.z);                                     \
    __nv_bfloat16 h3 = __float2bfloat16(v.w);                                     \
    __nv_bfloat16 l0 = __float2bfloat16(v.x - __bfloat162float(h0));              \
    __nv_bfloat16 l1 = __float2bfloat16(v.y - __bfloat162float(h1));              \
    __nv_bfloat16 l2 = __float2bfloat16(v.z - __bfloat162float(h2));              \
    __nv_bfloat16 l3 = __float2bfloat16(v.w - __bfloat162float(h3));              \
    __nv_bfloat162* Hi = (__nv_bfloat162*)(HI);                                   \
    __nv_bfloat162* Lo = (__nv_bfloat162*)(LO);                                   \
    Hi[2*i+0] = __nv_bfloat162(h0,h1);                                            \
    Hi[2*i+1] = __nv_bfloat162(h2,h3);                                            \
    Lo[2*i+0] = __nv_bfloat162(l0,l1);                                            \
    Lo[2*i+1] = __nv_bfloat162(l2,l3);

__global__ void k_cvtWout(const float* __restrict__ W){ CVT_BODY(g_WoutHi, g_WoutLo) }
__global__ void k_cvtWih (const float* __restrict__ W){ CVT_BODY(g_WihHi,  g_WihLo ) }
__global__ void k_cvtWhh (const float* __restrict__ W){ CVT_BODY(g_WhhHi,  g_WhhLo ) }
__global__ void k_cvtWw  (const float* __restrict__ W){ CVT_BODY(g_WwHi,   g_WwLo  ) }

// ---------------- tensor-core primitives --------------------------------------
__device__ __forceinline__ void ldsm4(unsigned &r0, unsigned &r1, unsigned &r2, unsigned &r3,
                                      unsigned addr){
    asm volatile("ldmatrix.sync.aligned.m8n8.x4.shared.b16 {%0,%1,%2,%3}, [%4];\n"
        : "=r"(r0),"=r"(r1),"=r"(r2),"=r"(r3) : "r"(addr));
}
__device__ __forceinline__ void mma_bf16(float* c, const unsigned* a, const unsigned* b){
    asm volatile("mma.sync.aligned.m16n8k16.row.col.f32.bf16.bf16.f32 "
        "{%0,%1,%2,%3}, {%4,%5,%6,%7}, {%8,%9}, {%0,%1,%2,%3};\n"
        : "+f"(c[0]),"+f"(c[1]),"+f"(c[2]),"+f"(c[3])
        : "r"(a[0]),"r"(a[1]),"r"(a[2]),"r"(a[3]), "r"(b[0]),"r"(b[1]));
}

#define SROW 40   // padded smem row stride in bf16 (80 bytes -> conflict-free ldmatrix)

// ---------------- XP GEMM (tensor core): Emb(2016x512) @ Wih^T + biases -------
__global__ void __launch_bounds__(256,1)
k_xp_mma(const float* __restrict__ bih, const float* __restrict__ bhh){
    __shared__ __align__(16) __nv_bfloat16 sAh[128*SROW];
    __shared__ __align__(16) __nv_bfloat16 sAl[128*SROW];
    __shared__ __align__(16) __nv_bfloat16 sBh[128*SROW];
    __shared__ __align__(16) __nv_bfloat16 sBl[128*SROW];

    const int bm = blockIdx.y*128, bn = blockIdx.x*128;
    const int tid = threadIdx.x, lane = tid & 31, warp = tid >> 5;
    const int wm = warp & 3, wn = warp >> 2;

    float acc[2][8][4];
    #pragma unroll
    for(int i=0;i<2;i++)
        #pragma unroll
        for(int j=0;j<8;j++){ acc[i][j][0]=0.f; acc[i][j][1]=0.f; acc[i][j][2]=0.f; acc[i][j][3]=0.f; }

    uint4 rAh[2], rAl[2], rBh[2], rBl[2];
    const uint4 z4 = make_uint4(0u,0u,0u,0u);

    unsigned uAh = (unsigned)__cvta_generic_to_shared(sAh);
    unsigned uAl = (unsigned)__cvta_generic_to_shared(sAl);
    unsigned uBh = (unsigned)__cvta_generic_to_shared(sBh);
    unsigned uBl = (unsigned)__cvta_generic_to_shared(sBl);

    int r0i = (tid*2) >> 2, s0 = (tid*2) & 3;
    int r1i = (tid*2+1) >> 2, s1 = (tid*2+1) & 3;

    #define LOADCH(ch) do{                                                        \
        size_t ko = (size_t)(ch)*32;                                              \
        bool ok0 = (bm+r0i) < MROWS, ok1 = (bm+r1i) < MROWS;                      \
        rAh[0] = ok0 ? *(const uint4*)(g_EmbHi + (size_t)(bm+r0i)*EMB + ko + s0*8) : z4; \
        rAl[0] = ok0 ? *(const uint4*)(g_EmbLo + (size_t)(bm+r0i)*EMB + ko + s0*8) : z4; \
        rAh[1] = ok1 ? *(const uint4*)(g_EmbHi + (size_t)(bm+r1i)*EMB + ko + s1*8) : z4; \
        rAl[1] = ok1 ? *(const uint4*)(g_EmbLo + (size_t)(bm+r1i)*EMB + ko + s1*8) : z4; \
        rBh[0] = *(const uint4*)(g_WihHi + (size_t)(bn+r0i)*EMB + ko + s0*8);     \
        rBl[0] = *(const uint4*)(g_WihLo + (size_t)(bn+r0i)*EMB + ko + s0*8);     \
        rBh[1] = *(const uint4*)(g_WihHi + (size_t)(bn+r1i)*EMB + ko + s1*8);     \
        rBl[1] = *(const uint4*)(g_WihLo + (size_t)(bn+r1i)*EMB + ko + s1*8);     \
    }while(0)

    LOADCH(0);

    for (int ch = 0; ch < 16; ch++){
        __syncthreads();
        *(uint4*)(sAh + r0i*SROW + s0*8) = rAh[0];
        *(uint4*)(sAl + r0i*SROW + s0*8) = rAl[0];
        *(uint4*)(sBh + r0i*SROW + s0*8) = rBh[0];
        *(uint4*)(sBl + r0i*SROW + s0*8) = rBl[0];
        *(uint4*)(sAh + r1i*SROW + s1*8) = rAh[1];
        *(uint4*)(sAl + r1i*SROW + s1*8) = rAl[1];
        *(uint4*)(sBh + r1i*SROW + s1*8) = rBh[1];
        *(uint4*)(sBl + r1i*SROW + s1*8) = rBl[1];
        __syncthreads();
        if (ch+1 < 16) LOADCH(ch+1);

        #pragma unroll
        for (int ks = 0; ks < 2; ks++){
            unsigned ah[2][4], al[2][4], bh[8][2], bl[8][2];
            int arow = wm*32 + (lane & 15);
            int acol = ks*16 + ((lane & 16) ? 8 : 0);
            #pragma unroll
            for (int mt = 0; mt < 2; mt++){
                unsigned off = (unsigned)((arow + mt*16)*SROW + acol) * 2u;
                ldsm4(ah[mt][0], ah[mt][1], ah[mt][2], ah[mt][3], uAh + off);
                ldsm4(al[mt][0], al[mt][1], al[mt][2], al[mt][3], uAl + off);
            }
            int brow = wn*64 + (lane & 7) + ((lane & 16) ? 8 : 0);
            int bcol = ks*16 + ((lane & 8) ? 8 : 0);
            #pragma unroll
            for (int p = 0; p < 4; p++){
                unsigned off = (unsigned)((brow + p*16)*SROW + bcol) * 2u;
                ldsm4(bh[2*p][0], bh[2*p][1], bh[2*p+1][0], bh[2*p+1][1], uBh + off);
                ldsm4(bl[2*p][0], bl[2*p][1], bl[2*p+1][0], bl[2*p+1][1], uBl + off);
            }
            #pragma unroll
            for (int mt = 0; mt < 2; mt++)
                #pragma unroll
                for (int nt = 0; nt < 8; nt++){
                    mma_bf16(acc[mt][nt], ah[mt], bh[nt]);
                    mma_bf16(acc[mt][nt], ah[mt], bl[nt]);
                    mma_bf16(acc[mt][nt], al[mt], bh[nt]);
                }
        }
    }

    #pragma unroll
    for (int mt = 0; mt < 2; mt++){
        int m0 = bm + wm*32 + mt*16 + (lane >> 2);
        int m1 = m0 + 8;
        #pragma unroll
        for (int nt = 0; nt < 8; nt++){
            int n = bn + wn*64 + nt*8 + (lane & 3)*2;
            float b0 = bih[n] + bhh[n], b1 = bih[n+1] + bhh[n+1];
            if (m0 < MROWS)
                *(float2*)(g_XP + (size_t)m0*GATES + n) =
                    make_float2(acc[mt][nt][0] + b0, acc[mt][nt][1] + b1);
            if (m1 < MROWS)
                *(float2*)(g_XP + (size_t)m1*GATES + n) =
                    make_float2(acc[mt][nt][2] + b0, acc[mt][nt][3] + b1);
        }
    }
    #undef LOADCH
}

// ---------------- tensor-core dec(t) + gates(t+1), 256 thr, double-buffered ----
// gates (blk 0..127):  g_gpart[Ks]    = h    @ Whh^T (M=32, N-tile 256, K-slice 128)
// dec   (blk 128..191): g_dpart[Ks][t] = hcat @ Ww^T  (M=32, N-tile 256, K-slice 128)
__global__ void __launch_bounds__(256,1)
k_dg_mma(int t){
    __shared__ __align__(16) __nv_bfloat16 sAh[2*32*SROW];
    __shared__ __align__(16) __nv_bfloat16 sAl[2*32*SROW];
    __shared__ __align__(16) __nv_bfloat16 sBh[2*256*SROW];
    __shared__ __align__(16) __nv_bfloat16 sBl[2*256*SROW];

    int blk = blockIdx.x;
    int tid = threadIdx.x, lane = tid & 31, wn = tid >> 5;   // 8 warps, 32 cols each
    int bn, Koff, Kdim, Nstr;
    const __nv_bfloat16 *Bh, *Bl;
    float* dst;
    if (blk < 128){   // gates: 16 N-tiles x 8 K-slices
        bn = (blk & 15)*256; Koff = (blk >> 4)*128; Kdim = HID; Nstr = GATES;
        Bh = g_WhhHi; Bl = g_WhhLo; dst = g_gpart[blk >> 4];
    } else {          // dec: 4 N-tiles x 16 K-slices
        int g = blk - 128;
        bn = (g & 3)*256; Koff = (g >> 2)*128; Kdim = HC; Nstr = HID;
        Bh = g_WwHi; Bl = g_WwLo; dst = g_dpart[g >> 2] + (size_t)t*BATCH*HID;
    }

    float acc[2][4][4];
    #pragma unroll
    for(int i=0;i<2;i++)
        #pragma unroll
        for(int j=0;j<4;j++){ acc[i][j][0]=0.f; acc[i][j][1]=0.f; acc[i][j][2]=0.f; acc[i][j][3]=0.f; }

    unsigned uAh = (unsigned)__cvta_generic_to_shared(sAh);
    unsigned uAl = (unsigned)__cvta_generic_to_shared(sAl);
    unsigned uBh = (unsigned)__cvta_generic_to_shared(sBh);
    unsigned uBl = (unsigned)__cvta_generic_to_shared(sBl);

    int tr = tid >> 2, seg = tid & 3;     // tr 0..63, seg 0..3 (32 cols per chunk)
    uint4 rAh4, rAl4, rBh[4], rBl[4];

    #define DGLOAD(ch) do{                                                        \
        int ko = Koff + (ch)*32 + seg*8;                                          \
        if (tid < 128){                                                           \
            rAh4 = *(const uint4*)(g_hcHi + (size_t)(tid>>2)*HC + ko);            \
            rAl4 = *(const uint4*)(g_hcLo + (size_t)(tid>>2)*HC + ko);            \
        }                                                                         \
        _Pragma("unroll")                                                         \
        for (int i = 0; i < 4; i++){                                              \
            int row = tr + 64*i;                                                  \
            rBh[i] = *(const uint4*)(Bh + (size_t)(bn+row)*Kdim + ko);            \
            rBl[i] = *(const uint4*)(Bl + (size_t)(bn+row)*Kdim + ko);            \
        }                                                                         \
    }while(0)

    DGLOAD(0);

    for (int ch = 0; ch < 4; ch++){
        int offA = (ch & 1)*32*SROW;
        int offB = (ch & 1)*256*SROW;
        if (tid < 128){
            *(uint4*)(sAh + offA + (tid>>2)*SROW + seg*8) = rAh4;
            *(uint4*)(sAl + offA + (tid>>2)*SROW + seg*8) = rAl4;
        }
        #pragma unroll
        for (int i = 0; i < 4; i++){
            int row = tr + 64*i;
            *(uint4*)(sBh + offB + row*SROW + seg*8) = rBh[i];
            *(uint4*)(sBl + offB + row*SROW + seg*8) = rBl[i];
        }
        __syncthreads();
        if (ch+1 < 4) DGLOAD(ch+1);

        #pragma unroll
        for (int ks = 0; ks < 2; ks++){
            unsigned ah[2][4], al[2][4], bh[4][2], bl[4][2];
            int arow = (lane & 15);                         // wm = 0
            int acol = ks*16 + ((lane & 16) ? 8 : 0);
            #pragma unroll
            for (int mt = 0; mt < 2; mt++){
                unsigned off = (unsigned)((offA + (arow + mt*16)*SROW + acol)) * 2u;
                ldsm4(ah[mt][0], ah[mt][1], ah[mt][2], ah[mt][3], uAh + off);
                ldsm4(al[mt][0], al[mt][1], al[mt][2], al[mt][3], uAl + off);
            }
            int brow = wn*32 + (lane & 7) + ((lane & 16) ? 8 : 0);
            int bcol = ks*16 + ((lane & 8) ? 8 : 0);
            #pragma unroll
            for (int p = 0; p < 2; p++){
                unsigned off = (unsigned)((offB + (brow + p*16)*SROW + bcol)) * 2u;
                ldsm4(bh[2*p][0], bh[2*p][1], bh[2*p+1][0], bh[2*p+1][1], uBh + off);
                ldsm4(bl[2*p][0], bl[2*p][1], bl[2*p+1][0], bl[2*p+1][1], uBl + off);
            }
            #pragma unroll
            for (int mt = 0; mt < 2; mt++)
                #pragma unroll
                for (int nt = 0; nt < 4; nt++){
                    mma_bf16(acc[mt][nt], ah[mt], bh[nt]);
                    mma_bf16(acc[mt][nt], ah[mt], bl[nt]);
                    mma_bf16(acc[mt][nt], al[mt], bh[nt]);
                }
        }
    }
    #undef DGLOAD

    // epilogue: fp32 partials (no bias)
    #pragma unroll
    for (int mt = 0; mt < 2; mt++){
        int m0 = mt*16 + (lane >> 2);
        int m1 = m0 + 8;
        #pragma unroll
        for (int nt = 0; nt < 4; nt++){
            int n = bn + wn*32 + nt*8 + (lane & 3)*2;
            *(float2*)(dst + (size_t)m0*Nstr + n) = make_float2(acc[mt][nt][0], acc[mt][nt][1]);
            *(float2*)(dst + (size_t)m1*Nstr + n) = make_float2(acc[mt][nt][2], acc[mt][nt][3]);
        }
    }
}

// ---------------- fused LSTM cell + scores + softmax + context -----------------
__global__ void __launch_bounds__(1024,1)
k_cellattn(const float* __restrict__ enc, int t){
    __shared__ float sh[HID];
    __shared__ float ss[SEQ];
    int b = blockIdx.x, j = threadIdx.x;       // j = 0..1023
    size_t gbase = (size_t)b*GATES;
    const float* xp = g_XP + ((size_t)t*BATCH + b)*GATES;
    float gi = xp[j], gf = xp[1024+j], gg = xp[2048+j], go = xp[3072+j];
    #pragma unroll
    for(int s=0;s<8;s++){
        const float* gp = g_gpart[s] + gbase;
        gi += gp[j]; gf += gp[1024+j]; gg += gp[2048+j]; go += gp[3072+j];
    }
    float i_ = 1.f/(1.f+expf(-gi));
    float f_ = 1.f/(1.f+expf(-gf));
    float g_ = tanhf(gg);
    float o_ = 1.f/(1.f+expf(-go));
    int idx  = b*HID + j;
    float c  = f_*g_c[idx] + i_*g_;
    g_c[idx] = c;
    float h  = o_*tanhf(c);
    {
        __nv_bfloat16 hi = __float2bfloat16(h);
        __nv_bfloat16 lo = __float2bfloat16(h - __bfloat162float(hi));
        g_hcHi[(size_t)b*HC + j] = hi;
        g_hcLo[(size_t)b*HC + j] = lo;
    }
    sh[j] = h;
    __syncthreads();
    // scores: 32 warps, warp w handles s = w, w+32
    int warp = j>>5, lane = j&31;
    for (int s=warp; s<SEQ; s+=32){
        const float* e = enc + ((size_t)b*SEQ + s)*HID;
        float acc = 0.f;
        #pragma unroll 8
        for (int k=lane;k<HID;k+=32) acc += sh[k]*e[k];
        #pragma unroll
        for(int o=16;o;o>>=1) acc += __shfl_xor_sync(0xffffffffu, acc, o);
        if (!lane) ss[s] = acc;
    }
    __syncthreads();
    if (j == 0){
        float mx = -1e30f;
        for(int s=0;s<SEQ;s++) mx = fmaxf(mx, ss[s]);
        float sum = 0.f;
        for(int s=0;s<SEQ;s++){ float e = expf(ss[s]-mx); ss[s]=e; sum+=e; }
        float inv = 1.f/sum;
        for(int s=0;s<SEQ;s++) ss[s] *= inv;
    }
    __syncthreads();
    // context: thread j handles hid column j
    const float* e = enc + (size_t)b*SEQ*HID + j;
    float ctx = 0.f;
    #pragma unroll 8
    for (int s=0;s<SEQ;s++) ctx += ss[s]*e[(size_t)s*HID];
    {
        __nv_bfloat16 hi = __float2bfloat16(ctx);
        __nv_bfloat16 lo = __float2bfloat16(ctx - __bfloat162float(hi));
        g_hcHi[(size_t)b*HC + HID + j] = hi;
        g_hcLo[(size_t)b*HC + HID + j] = lo;
    }
}

// ---------------- tanh reduce (16 slices) -> Dec bf16 hi/lo --------------------
__global__ void k_tanh(const float* __restrict__ bw){
    int idx = blockIdx.x*blockDim.x + threadIdx.x;   // 2016*1024
    float s = bw[idx & 1023];
    #pragma unroll
    for(int p=0;p<16;p++) s += g_dpart[p][idx];
    float th = tanhf(s);
    __nv_bfloat16 hi = __float2bfloat16(th);
    __nv_bfloat16 lo = __float2bfloat16(th - __bfloat162float(hi));
    g_DecHi[idx] = hi;
    g_DecLo[idx] = lo;
}

// ---------------- tensor-core output GEMM (double-buffered) --------------------
__global__ void __launch_bounds__(256,1)
k_out_mma(const float* __restrict__ bout, float* __restrict__ out){
    __shared__ __align__(16) __nv_bfloat16 sAh[2*128*SROW];
    __shared__ __align__(16) __nv_bfloat16 sAl[2*128*SROW];
    __shared__ __align__(16) __nv_bfloat16 sBh[2*128*SROW];
    __shared__ __align__(16) __nv_bfloat16 sBl[2*128*SROW];

    const int bm = blockIdx.y*128, bn = blockIdx.x*128;
    const int tid = threadIdx.x, lane = tid & 31, warp = tid >> 5;
    const int wm = warp & 3, wn = warp >> 2;

    float acc[2][8][4];
    #pragma unroll
    for(int i=0;i<2;i++)
        #pragma unroll
        for(int j=0;j<8;j++){ acc[i][j][0]=0.f; acc[i][j][1]=0.f; acc[i][j][2]=0.f; acc[i][j][3]=0.f; }

    uint4 rAh[2], rAl[2], rBh[2], rBl[2];
    const uint4 z4 = make_uint4(0u,0u,0u,0u);

    unsigned uAh = (unsigned)__cvta_generic_to_shared(sAh);
    unsigned uAl = (unsigned)__cvta_generic_to_shared(sAl);
    unsigned uBh = (unsigned)__cvta_generic_to_shared(sBh);
    unsigned uBl = (unsigned)__cvta_generic_to_shared(sBl);

    int r0i = (tid*2) >> 2, s0 = (tid*2) & 3;
    int r1i = (tid*2+1) >> 2, s1 = (tid*2+1) & 3;

    #define LOADCH(ch) do{                                                        \
        size_t ko = (size_t)(ch)*32;                                              \
        bool ok0 = (bm+r0i) < MROWS, ok1 = (bm+r1i) < MROWS;                      \
        rAh[0] = ok0 ? *(const uint4*)(g_DecHi + (size_t)(bm+r0i)*HID + ko + s0*8) : z4; \
        rAl[0] = ok0 ? *(const uint4*)(g_DecLo + (size_t)(bm+r0i)*HID + ko + s0*8) : z4; \
        rAh[1] = ok1 ? *(const uint4*)(g_DecHi + (size_t)(bm+r1i)*HID + ko + s1*8) : z4; \
        rAl[1] = ok1 ? *(const uint4*)(g_DecLo + (size_t)(bm+r1i)*HID + ko + s1*8) : z4; \
        rBh[0] = *(const uint4*)(g_WoutHi + (size_t)(bn+r0i)*HID + ko + s0*8);    \
        rBl[0] = *(const uint4*)(g_WoutLo + (size_t)(bn+r0i)*HID + ko + s0*8);    \
        rBh[1] = *(const uint4*)(g_WoutHi + (size_t)(bn+r1i)*HID + ko + s1*8);    \
        rBl[1] = *(const uint4*)(g_WoutLo + (size_t)(bn+r1i)*HID + ko + s1*8);    \
    }while(0)

    LOADCH(0);

    for (int ch = 0; ch < 32; ch++){
        int off = (ch & 1)*128*SROW;
        *(uint4*)(sAh + off + r0i*SROW + s0*8) = rAh[0];
        *(uint4*)(sAl + off + r0i*SROW + s0*8) = rAl[0];
        *(uint4*)(sBh + off + r0i*SROW + s0*8) = rBh[0];
        *(uint4*)(sBl + off + r0i*SROW + s0*8) = rBl[0];
        *(uint4*)(sAh + off + r1i*SROW + s1*8) = rAh[1];
        *(uint4*)(sAl + off + r1i*SROW + s1*8) = rAl[1];
        *(uint4*)(sBh + off + r1i*SROW + s1*8) = rBh[1];
        *(uint4*)(sBl + off + r1i*SROW + s1*8) = rBl[1];
        __syncthreads();
        if (ch+1 < 32) LOADCH(ch+1);

        #pragma unroll
        for (int ks = 0; ks < 2; ks++){
            unsigned ah[2][4], al[2][4], bh[8][2], bl[8][2];
            int arow = wm*32 + (lane & 15);
            int acol = ks*16 + ((lane & 16) ? 8 : 0);
            #pragma unroll
            for (int mt = 0; mt < 2; mt++){
                unsigned o2 = (unsigned)((off + (arow + mt*16)*SROW + acol)) * 2u;
                ldsm4(ah[mt][0], ah[mt][1], ah[mt][2], ah[mt][3], uAh + o2);
                ldsm4(al[mt][0], al[mt][1], al[mt][2], al[mt][3], uAl + o2);
            }
            int brow = wn*64 + (lane & 7) + ((lane & 16) ? 8 : 0);
            int bcol = ks*16 + ((lane & 8) ? 8 : 0);
            #pragma unroll
            for (int p = 0; p < 4; p++){
                unsigned o2 = (unsigned)((off + (brow + p*16)*SROW + bcol)) * 2u;
                ldsm4(bh[2*p][0], bh[2*p][1], bh[2*p+1][0], bh[2*p+1][1], uBh + o2);
                ldsm4(bl[2*p][0], bl[2*p][1], bl[2*p+1][0], bl[2*p+1][1], uBl + o2);
            }
            #pragma unroll
            for (int mt = 0; mt < 2; mt++)
                #pragma unroll
                for (int nt = 0; nt < 8; nt++){
                    mma_bf16(acc[mt][nt], ah[mt], bh[nt]);
                    mma_bf16(acc[mt][nt], ah[mt], bl[nt]);
                    mma_bf16(acc[mt][nt], al[mt], bh[nt]);
                }
        }
    }

    #pragma unroll
    for (int mt = 0; mt < 2; mt++){
        int m0 = bm + wm*32 + mt*16 + (lane >> 2);
        int m1 = m0 + 8;
        #pragma unroll
        for (int nt = 0; nt < 8; nt++){
            int n = bn + wn*64 + nt*8 + (lane & 3)*2;
            float b0 = bout[n], b1 = bout[n+1];
            if (m0 < MROWS){
                int t = m0 >> 5, b = m0 & 31;
                float2 v = make_float2(acc[mt][nt][0] + b0, acc[mt][nt][1] + b1);
                *(float2*)(out + (size_t)b*(TSTEPS*VOC) + (size_t)t*VOC + n) = v;
            }
            if (m1 < MROWS){
                int t = m1 >> 5, b = m1 & 31;
                float2 v = make_float2(acc[mt][nt][2] + b0, acc[mt][nt][3] + b1);
                *(float2*)(out + (size_t)b*(TSTEPS*VOC) + (size_t)t*VOC + n) = v;
            }
        }
    }
    #undef LOADCH
}

// ---------------- launch ------------------------------------------------------
extern "C" void kernel_launch(void* const* d_in, const int* in_sizes, int n_in,
                              void* d_out, int out_size){
    const int*   tgt  = (const int*)  d_in[0];
    const float* h0   = (const float*)d_in[1];
    const float* c0   = (const float*)d_in[2];
    const float* enc  = (const float*)d_in[3];
    const float* emb  = (const float*)d_in[4];
    const float* Wih  = (const float*)d_in[5];
    const float* Whh  = (const float*)d_in[6];
    const float* bih  = (const float*)d_in[7];
    const float* bhh  = (const float*)d_in[8];
    const float* Ww   = (const float*)d_in[9];
    const float* bw   = (const float*)d_in[10];
    const float* Wout = (const float*)d_in[11];
    const float* bout = (const float*)d_in[12];
    float* out = (float*)d_out;

    k_init   <<<128, 256>>>(h0, c0);
    k_embed  <<<MROWS, 128>>>(tgt, emb);
    k_cvtWout<<<((size_t)VOC*HID/4)/256, 256>>>(Wout);
    k_cvtWih <<<((size_t)GATES*EMB/4)/256, 256>>>(Wih);
    k_cvtWhh <<<((size_t)GATES*HID/4)/256, 256>>>(Whh);
    k_cvtWw  <<<((size_t)HID*HC/4)/256, 256>>>(Ww);
    k_xp_mma <<<dim3(GATES/128, (MROWS+127)/128), 256>>>(bih, bhh);

    k_dg_mma<<<128, 256>>>(0);                  // prolog: gates(0) only
    for (int t = 0; t < TSTEPS; t++){
        k_cellattn<<<BATCH, 1024>>>(enc, t);
        k_dg_mma  <<<192, 256>>>(t);            // dec(t) + gates(t+1)
    }

    k_tanh<<<(MROWS*HID)/256, 256>>>(bw);
    k_out_mma<<<dim3(VOC/128, (MROWS+127)/128), 256>>>(bout, out);
}